// round 9
// baseline (speedup 1.0000x reference)
#include <cuda_runtime.h>
#include <math.h>
#include <stdint.h>

#define B_     8192
#define OBS_   128
#define LAT_   32
#define NXT_   128
#define E_     8
#define HG_    256
#define H_     256
#define DIN_   (OBS_ + LAT_)   // 160
#define IN1_   (H_ + LAT_)     // 288

// ---------------- device scratch ----------------
__device__ float g_xz [B_ * DIN_];
__device__ float g_g0 [B_ * HG_];
__device__ float g_g1 [B_ * HG_];
__device__ float g_g2 [B_ * HG_];
__device__ float g_h1 [B_ * IN1_];
__device__ float g_h2 [B_ * IN1_];
__device__ float g_coef[B_ * E_];
// fragment-major weights (+ bias tile folded in as last k-tile)
__device__ float g_f0 [2 * 41 * 4096];
__device__ float g_f1 [2 * 73 * 4096];
__device__ float g_f2 [2 * 73 * 2048];
__device__ float g_fg0[2 * 16 * 4096];
__device__ float g_fg1[2 * 25 * 4096];
__device__ float g_fg2[2 * 25 * 4096];

// ---------------- helpers ----------------
__device__ __forceinline__ uint32_t smem_u32(const void* p) {
    uint32_t a;
    asm("{ .reg .u64 t; cvta.to.shared.u64 t, %1; cvt.u32.u64 %0, t; }" : "=r"(a) : "l"(p));
    return a;
}
__device__ __forceinline__ uint32_t tf32u(float x) {
    uint32_t r;
    asm("cvt.rna.tf32.f32 %0, %1;" : "=r"(r) : "f"(x));
    return r;
}
#define CP_ASYNC16(dst, src) \
    asm volatile("cp.async.cg.shared.global [%0], [%1], 16;" :: "r"(dst), "l"(src) : "memory")
#define CP_COMMIT() asm volatile("cp.async.commit_group;" ::: "memory")
#define CP_WAIT0()  asm volatile("cp.async.wait_group 0;" ::: "memory")
#define CP_WAIT1()  asm volatile("cp.async.wait_group 1;" ::: "memory")

#define MMA_TF32(d, a, b)                                                          \
    asm volatile("mma.sync.aligned.m16n8k8.row.col.f32.tf32.tf32.f32 "             \
        "{%0,%1,%2,%3}, {%4,%5,%6,%7}, {%8,%9}, {%0,%1,%2,%3};"                    \
        : "+f"((d)[0]), "+f"((d)[1]), "+f"((d)[2]), "+f"((d)[3])                   \
        : "r"((a)[0]), "r"((a)[1]), "r"((a)[2]), "r"((a)[3]),                      \
          "r"((b)[0]), "r"((b)[1]))

// ---------------- pack ----------------
__global__ void pack_kernel(const float* __restrict__ x, const float* __restrict__ z)
{
    int stride = gridDim.x * blockDim.x;
    int idx = blockIdx.x * blockDim.x + threadIdx.x;
    for (int t = idx; t < B_ * DIN_; t += stride) {
        int b = t / DIN_, c = t - b * DIN_;
        g_xz[t] = (c < OBS_) ? x[b * OBS_ + c] : z[b * LAT_ + (c - OBS_)];
    }
    for (int t = idx; t < B_ * LAT_; t += stride) {
        int b = t / LAT_, c = t - b * LAT_;
        float v = z[t];
        g_h1[b * IN1_ + H_ + c] = v;
        g_h2[b * IN1_ + H_ + c] = v;
    }
}

// ---------------- weight -> fragment-major (bias tile appended) ----------------
// Word index within a tile (CHUNK = BN*32 words):
//   w = ((cg*4 + k8)*4 + nt)*64 + lid*2 + jj,  lid = g*4 + tig
//   k    = k8*8 + jj*4 + tig
//   col  = nblk*BN + cg*32 + nt*8 + g
// MODE 0: expert W[K,N] rna-tf32; bias tile rows kloc<E_.
// MODE 1: gating 3x split [Wh;Wh;Wl]; bias tile row kloc==0.
template<int MODE, int BN>
__global__ void wfrag_kernel(const float* __restrict__ W, const float* __restrict__ bias,
                             float* __restrict__ dst, int N, int NT, int HT)
{
    const int CHUNK = BN * 32;
    const int NTT = NT + 1;
    int total = (N / BN) * NTT * CHUNK;
    for (int idx = blockIdx.x * blockDim.x + threadIdx.x; idx < total;
         idx += gridDim.x * blockDim.x) {
        int nblk = idx / (NTT * CHUNK);
        int r = idx - nblk * NTT * CHUNK;
        int t = r / CHUNK;
        int w = r - t * CHUNK;
        int jj  = w & 1;
        int lid = (w >> 1) & 31;
        int g   = lid >> 2, tig = lid & 3;
        int grp = w >> 6;
        int nt  = grp & 3, k8 = (grp >> 2) & 3, cg = grp >> 4;
        int kloc = k8 * 8 + jj * 4 + tig;
        int col  = nblk * BN + cg * 32 + nt * 8 + g;
        float val;
        if (t < NT) {
            if (MODE == 0) {
                val = __uint_as_float(tf32u(W[(size_t)(t * 32 + kloc) * N + col]));
            } else {
                int kv = t * 32 + kloc;
                int p = kv / (HT * 32);
                int ko = kv - p * HT * 32;
                float a = W[(size_t)ko * N + col];
                uint32_t hi = tf32u(a);
                val = (p < 2) ? __uint_as_float(hi)
                              : __uint_as_float(tf32u(a - __uint_as_float(hi)));
            }
        } else {
            if (MODE == 0) val = (kloc < E_) ? __uint_as_float(tf32u(bias[kloc * N + col])) : 0.f;
            else           val = (kloc == 0) ? __uint_as_float(tf32u(bias[col])) : 0.f;
        }
        dst[idx] = val;
    }
}

// ---------------- gating head + softmax (fp32) ----------------
__global__ __launch_bounds__(256)
void coef_kernel(const float* __restrict__ g2,
                 const float* __restrict__ gw3, const float* __restrict__ gb3)
{
    __shared__ float w_s[HG_ * 9];
    for (int i = threadIdx.x; i < HG_ * E_; i += blockDim.x)
        w_s[(i / E_) * 9 + (i % E_)] = gw3[i];
    __syncthreads();
    int lane = threadIdx.x & 31;
    int warp = (blockIdx.x * blockDim.x + threadIdx.x) >> 5;
    int nwarps = (gridDim.x * blockDim.x) >> 5;
    for (int b = warp; b < B_; b += nwarps) {
        float acc[E_] = {};
        for (int i = lane; i < HG_; i += 32) {
            float v = g2[(size_t)b * HG_ + i];
            const float* wr = &w_s[i * 9];
#pragma unroll
            for (int e = 0; e < E_; e++) acc[e] = fmaf(v, wr[e], acc[e]);
        }
#pragma unroll
        for (int e = 0; e < E_; e++)
#pragma unroll
            for (int off = 16; off; off >>= 1)
                acc[e] += __shfl_xor_sync(0xFFFFFFFFu, acc[e], off);
        if (lane == 0) {
            float mx = -1e30f;
#pragma unroll
            for (int e = 0; e < E_; e++) { acc[e] += gb3[e]; mx = fmaxf(mx, acc[e]); }
            float s = 0.f;
#pragma unroll
            for (int e = 0; e < E_; e++) { acc[e] = expf(acc[e] - mx); s += acc[e]; }
            float inv = 1.f / s;
#pragma unroll
            for (int e = 0; e < E_; e++) g_coef[b * E_ + e] = acc[e] * inv;
        }
    }
}

// ---------------- tensor GEMM: BM=64, frag-major B, 3 CTAs/SM ----------------
template<int MODE, int IN, int NT, int BN, int ACT>
__global__ __launch_bounds__(256, 3)
void mma_kernel(const float* __restrict__ A, int lda,
                const float* __restrict__ Wf,
                const float* __restrict__ coef,
                float* __restrict__ Cout, int ldc)
{
    constexpr int BM = 64, NTT = NT + 1, ASTR = 36;
    constexpr int CHUNK = BN * 32;
    constexpr int ABYTES = BM * ASTR * 4, BBYTES = CHUNK * 4;
    constexpr int WCOLS = BN / 32, WROWS = 8 / WCOLS, MT = BM / (WROWS * 16);

    extern __shared__ char smem[];
    float* coef_s = (float*)smem;
    const int offA[2] = {2048, 2048 + ABYTES};
    const int offB0 = 2048 + 2 * ABYTES;
    const uint32_t sb = smem_u32(smem);

    const int tid = threadIdx.x, wid = tid >> 5, lid = tid & 31;
    const int g = lid >> 2, tig = lid & 3;
    const int m0 = blockIdx.y * BM, n0 = blockIdx.x * BN;
    const int rbase = (wid / WCOLS) * (MT * 16);
    const int cgw = wid % WCOLS;
    const int arow = tid >> 2, ak8 = (tid & 3) * 8;
    const float* Wblk = Wf + (size_t)blockIdx.x * NTT * CHUNK;

    if (MODE == 0)
        for (int i = tid; i < BM * E_; i += 256) coef_s[i] = coef[m0 * E_ + i];
    __syncthreads();

    auto cpB = [&](int t, int buf) {
#pragma unroll
        for (int i = 0; i < BN / 32; i++) {
            int off = tid + 256 * i;
            CP_ASYNC16(sb + offB0 + buf * BBYTES + off * 16, Wblk + t * CHUNK + off * 4);
        }
        CP_COMMIT();
    };
    auto ldA = [&](int t, float4* pa) {
        const int i0 = (t * 32) % IN;
        const float* ap = A + (size_t)(m0 + arow) * lda + i0 + ak8;
        pa[0] = *(const float4*)ap;
        pa[1] = *(const float4*)(ap + 4);
    };
    auto stA = [&](int t, int buf, const float4* pa) {
        const int p = (t * 32) / IN;
        float* As = (float*)(smem + offA[buf]);
#pragma unroll
        for (int a = 0; a < 2; a++) {
            uint4 u;
            const float* pv = (const float*)&pa[a];
            uint32_t* uu = (uint32_t*)&u;
            if (MODE == 0) {
                float s = coef_s[arow * E_ + p];
#pragma unroll
                for (int q = 0; q < 4; q++) uu[q] = tf32u(pv[q] * s);
            } else if (p == 1) {
#pragma unroll
                for (int q = 0; q < 4; q++) {
                    uint32_t hi = tf32u(pv[q]);
                    uu[q] = tf32u(pv[q] - __uint_as_float(hi));
                }
            } else {
#pragma unroll
                for (int q = 0; q < 4; q++) uu[q] = tf32u(pv[q]);
            }
            *(uint4*)(As + arow * ASTR + ak8 + 4 * a) = u;
        }
    };
    auto stSpecA = [&](int buf) {
        float* As = (float*)(smem + offA[buf]);
#pragma unroll
        for (int a = 0; a < 2; a++) {
            uint4 u = {0u, 0u, 0u, 0u};
            uint32_t* uu = (uint32_t*)&u;
#pragma unroll
            for (int q = 0; q < 4; q++) {
                int k = ak8 + 4 * a + q;
                if (MODE == 0) { if (k < E_) uu[q] = tf32u(coef_s[arow * E_ + k]); }
                else           { if (k == 0) uu[q] = 0x3f800000u; }
            }
            *(uint4*)(As + arow * ASTR + ak8 + 4 * a) = u;
        }
    };

    float acc[MT][4][4] = {};

    cpB(0, 0);
    cpB(1, 1);
    float4 pa[2];
    ldA(0, pa);
    stA(0, 0, pa);
    CP_WAIT1();
    __syncthreads();

    for (int t = 0; t < NTT; t++) {
        const int abuf = t & 1, bbuf = t % 3;
        if (t + 2 < NTT) cpB(t + 2, (t + 2) % 3);
        const bool nxt = (t + 1 < NTT), nrm = (t + 1 < NT);
        if (nxt && nrm) ldA(t + 1, pa);

        {
            const uint32_t* Asu = (const uint32_t*)(smem + offA[abuf]);
            const char* Bbase = smem + offB0 + bbuf * BBYTES;
#pragma unroll
            for (int k8 = 0; k8 < 4; k8++) {
                uint32_t af[MT][4], bf[4][2];
#pragma unroll
                for (int mt = 0; mt < MT; mt++) {
                    const int r0 = rbase + mt * 16 + g;
                    const int kk = k8 * 8 + tig;
                    af[mt][0] = Asu[r0 * ASTR + kk];
                    af[mt][1] = Asu[(r0 + 8) * ASTR + kk];
                    af[mt][2] = Asu[r0 * ASTR + kk + 4];
                    af[mt][3] = Asu[(r0 + 8) * ASTR + kk + 4];
                }
#pragma unroll
                for (int nt = 0; nt < 4; nt++)
                    *(uint2*)bf[nt] = *(const uint2*)(Bbase +
                        ((((cgw * 4 + k8) * 4 + nt) * 64) + lid * 2) * 4);
#pragma unroll
                for (int mt = 0; mt < MT; mt++)
#pragma unroll
                    for (int nt = 0; nt < 4; nt++)
                        MMA_TF32(acc[mt][nt], af[mt], bf[nt]);
            }
        }

        if (nxt) {
            if (nrm) stA(t + 1, abuf ^ 1, pa);
            else     stSpecA(abuf ^ 1);
            if (t + 2 < NTT) CP_WAIT1(); else CP_WAIT0();
            __syncthreads();
        }
    }

#pragma unroll
    for (int mt = 0; mt < MT; mt++) {
        const int r = m0 + rbase + mt * 16 + g;
#pragma unroll
        for (int nt = 0; nt < 4; nt++) {
            const int c = n0 + cgw * 32 + nt * 8 + 2 * tig;
            float2 v0, v1;
            v0.x = acc[mt][nt][0]; v0.y = acc[mt][nt][1];
            v1.x = acc[mt][nt][2]; v1.y = acc[mt][nt][3];
            if (ACT == 1) {
                v0.x = (v0.x > 0.f) ? v0.x : expm1f(v0.x);
                v0.y = (v0.y > 0.f) ? v0.y : expm1f(v0.y);
                v1.x = (v1.x > 0.f) ? v1.x : expm1f(v1.x);
                v1.y = (v1.y > 0.f) ? v1.y : expm1f(v1.y);
            }
            *(float2*)(Cout + (size_t)r * ldc + c)       = v0;
            *(float2*)(Cout + (size_t)(r + 8) * ldc + c) = v1;
        }
    }
}

// ---------------- launch ----------------
extern "C" void kernel_launch(void* const* d_in, const int* in_sizes, int n_in,
                              void* d_out, int out_size)
{
    const float* x   = (const float*)d_in[0];
    const float* z   = (const float*)d_in[1];
    const float* gw0 = (const float*)d_in[2];
    const float* gb0 = (const float*)d_in[3];
    const float* gw1 = (const float*)d_in[4];
    const float* gb1 = (const float*)d_in[5];
    const float* gw2 = (const float*)d_in[6];
    const float* gb2 = (const float*)d_in[7];
    const float* gw3 = (const float*)d_in[8];
    const float* gb3 = (const float*)d_in[9];
    const float* w0  = (const float*)d_in[10];
    const float* b0  = (const float*)d_in[11];
    const float* w1  = (const float*)d_in[12];
    const float* b1  = (const float*)d_in[13];
    const float* w2  = (const float*)d_in[14];
    const float* b2  = (const float*)d_in[15];
    float* out = (float*)d_out;

    float *xz, *g0, *g1, *g2, *h1, *h2, *coef, *f0, *f1, *f2, *fg0, *fg1, *fg2;
    cudaGetSymbolAddress((void**)&xz, g_xz);
    cudaGetSymbolAddress((void**)&g0, g_g0);
    cudaGetSymbolAddress((void**)&g1, g_g1);
    cudaGetSymbolAddress((void**)&g2, g_g2);
    cudaGetSymbolAddress((void**)&h1, g_h1);
    cudaGetSymbolAddress((void**)&h2, g_h2);
    cudaGetSymbolAddress((void**)&coef, g_coef);
    cudaGetSymbolAddress((void**)&f0, g_f0);
    cudaGetSymbolAddress((void**)&f1, g_f1);
    cudaGetSymbolAddress((void**)&f2, g_f2);
    cudaGetSymbolAddress((void**)&fg0, g_fg0);
    cudaGetSymbolAddress((void**)&fg1, g_fg1);
    cudaGetSymbolAddress((void**)&fg2, g_fg2);

    const int SM128 = 2048 + 2 * 9216 + 3 * 16384;  // 69632
    const int SM64  = 2048 + 2 * 9216 + 3 * 8192;   // 45056
    cudaFuncSetAttribute(mma_kernel<1, DIN_, 15, 128, 1>, cudaFuncAttributeMaxDynamicSharedMemorySize, SM128);
    cudaFuncSetAttribute(mma_kernel<1, HG_,  24, 128, 1>, cudaFuncAttributeMaxDynamicSharedMemorySize, SM128);
    cudaFuncSetAttribute(mma_kernel<0, DIN_, 40, 128, 1>, cudaFuncAttributeMaxDynamicSharedMemorySize, SM128);
    cudaFuncSetAttribute(mma_kernel<0, IN1_, 72, 128, 1>, cudaFuncAttributeMaxDynamicSharedMemorySize, SM128);
    cudaFuncSetAttribute(mma_kernel<0, IN1_, 72, 64,  0>, cudaFuncAttributeMaxDynamicSharedMemorySize, SM64);

    pack_kernel<<<1024, 256>>>(x, z);
    wfrag_kernel<0, 128><<<328, 256>>>(w0, b0, f0, 256, 40, 0);
    wfrag_kernel<0, 128><<<584, 256>>>(w1, b1, f1, 256, 72, 0);
    wfrag_kernel<0, 64> <<<292, 256>>>(w2, b2, f2, 128, 72, 0);
    wfrag_kernel<1, 128><<<128, 256>>>(gw0, gb0, fg0, 256, 15, 5);
    wfrag_kernel<1, 128><<<200, 256>>>(gw1, gb1, fg1, 256, 24, 8);
    wfrag_kernel<1, 128><<<200, 256>>>(gw2, gb2, fg2, 256, 24, 8);

    mma_kernel<1, DIN_, 15, 128, 1><<<dim3(2, 128), 256, SM128>>>(xz, DIN_, fg0, nullptr, g0, HG_);
    mma_kernel<1, HG_, 24, 128, 1><<<dim3(2, 128), 256, SM128>>>(g0, HG_, fg1, nullptr, g1, HG_);
    mma_kernel<1, HG_, 24, 128, 1><<<dim3(2, 128), 256, SM128>>>(g1, HG_, fg2, nullptr, g2, HG_);
    coef_kernel<<<128, 256>>>(g2, gw3, gb3);

    mma_kernel<0, DIN_, 40, 128, 1><<<dim3(2, 128), 256, SM128>>>(xz, DIN_, f0, coef, h1, IN1_);
    mma_kernel<0, IN1_, 72, 128, 1><<<dim3(2, 128), 256, SM128>>>(h1, IN1_, f1, coef, h2, IN1_);
    mma_kernel<0, IN1_, 72, 64, 0><<<dim3(2, 128), 256, SM64>>>(h2, IN1_, f2, coef, out, NXT_);
}

// round 10
// speedup vs baseline: 1.2340x; 1.2340x over previous
#include <cuda_runtime.h>
#include <math.h>
#include <stdint.h>

#define B_     8192
#define OBS_   128
#define LAT_   32
#define NXT_   128
#define E_     8
#define HG_    256
#define H_     256
#define DIN_   (OBS_ + LAT_)   // 160
#define IN1_   (H_ + LAT_)     // 288

// ---------------- device scratch ----------------
__device__ float g_xz [B_ * DIN_];
__device__ float g_g0 [B_ * HG_];
__device__ float g_g1 [B_ * HG_];
__device__ float g_g2 [B_ * HG_];
__device__ float g_h1 [B_ * IN1_];
__device__ float g_h2 [B_ * IN1_];
__device__ float g_coef[B_ * E_];
// fragment-major weights (+ bias tile folded in as last k-tile)
__device__ float g_f0 [2 * 41 * 4096];
__device__ float g_f1 [2 * 73 * 4096];
__device__ float g_f2 [2 * 73 * 2048];
__device__ float g_fg0[2 *  6 * 4096];
__device__ float g_fg1[2 *  9 * 4096];
__device__ float g_fg2[2 *  9 * 4096];

// ---------------- helpers ----------------
__device__ __forceinline__ uint32_t smem_u32(const void* p) {
    uint32_t a;
    asm("{ .reg .u64 t; cvta.to.shared.u64 t, %1; cvt.u32.u64 %0, t; }" : "=r"(a) : "l"(p));
    return a;
}
__device__ __forceinline__ uint32_t tf32u(float x) {
    uint32_t r;
    asm("cvt.rna.tf32.f32 %0, %1;" : "=r"(r) : "f"(x));
    return r;
}
#define CP_ASYNC16(dst, src) \
    asm volatile("cp.async.cg.shared.global [%0], [%1], 16;" :: "r"(dst), "l"(src) : "memory")
#define CP_COMMIT() asm volatile("cp.async.commit_group;" ::: "memory")
#define CP_WAIT0()  asm volatile("cp.async.wait_group 0;" ::: "memory")
#define CP_WAIT1()  asm volatile("cp.async.wait_group 1;" ::: "memory")

#define MMA_TF32(d, a, b)                                                          \
    asm volatile("mma.sync.aligned.m16n8k8.row.col.f32.tf32.tf32.f32 "             \
        "{%0,%1,%2,%3}, {%4,%5,%6,%7}, {%8,%9}, {%0,%1,%2,%3};"                    \
        : "+f"((d)[0]), "+f"((d)[1]), "+f"((d)[2]), "+f"((d)[3])                   \
        : "r"((a)[0]), "r"((a)[1]), "r"((a)[2]), "r"((a)[3]),                      \
          "r"((b)[0]), "r"((b)[1]))

// ---------------- pack ----------------
__global__ void pack_kernel(const float* __restrict__ x, const float* __restrict__ z)
{
    int stride = gridDim.x * blockDim.x;
    int idx = blockIdx.x * blockDim.x + threadIdx.x;
    for (int t = idx; t < B_ * DIN_; t += stride) {
        int b = t / DIN_, c = t - b * DIN_;
        g_xz[t] = (c < OBS_) ? x[b * OBS_ + c] : z[b * LAT_ + (c - OBS_)];
    }
    for (int t = idx; t < B_ * LAT_; t += stride) {
        int b = t / LAT_, c = t - b * LAT_;
        float v = z[t];
        g_h1[b * IN1_ + H_ + c] = v;
        g_h2[b * IN1_ + H_ + c] = v;
    }
}

// ---------------- fused weight -> fragment-major (bias tile appended) ----------------
// Word index within a tile (CHUNK = BN*32 words):
//   w = ((cg*4 + k8)*4 + nt)*64 + lid*2 + jj,  lid = g*4 + tig
//   k = k8*8 + jj*4 + tig ; col = nblk*BN + cg*32 + nt*8 + g
// W[K,N] rna-tf32; bias tile rows kloc < NB (NB=E_ for experts, 1 for gating vector).
__device__ void wfrag_seg(const float* __restrict__ W, const float* __restrict__ bias,
                          float* __restrict__ dst, int N, int NT, int NB, int BN,
                          int idx, int stride)
{
    const int CHUNK = BN * 32;
    const int NTT = NT + 1;
    int total = (N / BN) * NTT * CHUNK;
    for (int i = idx; i < total; i += stride) {
        int nblk = i / (NTT * CHUNK);
        int r = i - nblk * NTT * CHUNK;
        int t = r / CHUNK;
        int w = r - t * CHUNK;
        int jj  = w & 1;
        int lid = (w >> 1) & 31;
        int g   = lid >> 2, tig = lid & 3;
        int grp = w >> 6;
        int nt  = grp & 3, k8 = (grp >> 2) & 3, cg = grp >> 4;
        int kloc = k8 * 8 + jj * 4 + tig;
        int col  = nblk * BN + cg * 32 + nt * 8 + g;
        float val;
        if (t < NT)
            val = __uint_as_float(tf32u(W[(size_t)(t * 32 + kloc) * N + col]));
        else
            val = (kloc < NB) ? __uint_as_float(tf32u(bias[kloc * N + col])) : 0.f;
        dst[i] = val;
    }
}
__global__ void wprep_kernel(const float* w0, const float* b0,
                             const float* w1, const float* b1,
                             const float* w2, const float* b2,
                             const float* gw0, const float* gb0,
                             const float* gw1, const float* gb1,
                             const float* gw2, const float* gb2)
{
    int idx = blockIdx.x * blockDim.x + threadIdx.x;
    int stride = gridDim.x * blockDim.x;
    wfrag_seg(w0,  b0,  g_f0,  256, 40, E_, 128, idx, stride);
    wfrag_seg(w1,  b1,  g_f1,  256, 72, E_, 128, idx, stride);
    wfrag_seg(w2,  b2,  g_f2,  128, 72, E_,  64, idx, stride);
    wfrag_seg(gw0, gb0, g_fg0, 256,  5, 1,  128, idx, stride);
    wfrag_seg(gw1, gb1, g_fg1, 256,  8, 1,  128, idx, stride);
    wfrag_seg(gw2, gb2, g_fg2, 256,  8, 1,  128, idx, stride);
}

// ---------------- gating head + softmax (fp32) ----------------
__global__ __launch_bounds__(256)
void coef_kernel(const float* __restrict__ g2,
                 const float* __restrict__ gw3, const float* __restrict__ gb3)
{
    __shared__ float w_s[HG_ * 9];
    for (int i = threadIdx.x; i < HG_ * E_; i += blockDim.x)
        w_s[(i / E_) * 9 + (i % E_)] = gw3[i];
    __syncthreads();
    int lane = threadIdx.x & 31;
    int warp = (blockIdx.x * blockDim.x + threadIdx.x) >> 5;
    int nwarps = (gridDim.x * blockDim.x) >> 5;
    for (int b = warp; b < B_; b += nwarps) {
        float acc[E_] = {};
        for (int i = lane; i < HG_; i += 32) {
            float v = g2[(size_t)b * HG_ + i];
            const float* wr = &w_s[i * 9];
#pragma unroll
            for (int e = 0; e < E_; e++) acc[e] = fmaf(v, wr[e], acc[e]);
        }
#pragma unroll
        for (int e = 0; e < E_; e++)
#pragma unroll
            for (int off = 16; off; off >>= 1)
                acc[e] += __shfl_xor_sync(0xFFFFFFFFu, acc[e], off);
        if (lane == 0) {
            float mx = -1e30f;
#pragma unroll
            for (int e = 0; e < E_; e++) { acc[e] += gb3[e]; mx = fmaxf(mx, acc[e]); }
            float s = 0.f;
#pragma unroll
            for (int e = 0; e < E_; e++) { acc[e] = expf(acc[e] - mx); s += acc[e]; }
            float inv = 1.f / s;
#pragma unroll
            for (int e = 0; e < E_; e++) g_coef[b * E_ + e] = acc[e] * inv;
        }
    }
}

// ---------------- tensor GEMM: BM=64, frag-major B ----------------
// SCALE 1 (expert): C = act([coef*A | coef] @ [[W];[bias_E]])
// SCALE 0 (plain) : C = act([A | 1] @ [[W];[bias]])
template<int SCALE, int IN, int NT, int BN, int ACT>
__global__ __launch_bounds__(256, 3)
void mma_kernel(const float* __restrict__ A, int lda,
                const float* __restrict__ Wf,
                const float* __restrict__ coef,
                float* __restrict__ Cout, int ldc)
{
    constexpr int BM = 64, NTT = NT + 1, ASTR = 36;
    constexpr int CHUNK = BN * 32;
    constexpr int ABYTES = BM * ASTR * 4, BBYTES = CHUNK * 4;
    constexpr int WCOLS = BN / 32, WROWS = 8 / WCOLS, MT = BM / (WROWS * 16);

    extern __shared__ char smem[];
    float* coef_s = (float*)smem;
    const int offA[2] = {2048, 2048 + ABYTES};
    const int offB0 = 2048 + 2 * ABYTES;
    const uint32_t sb = smem_u32(smem);

    const int tid = threadIdx.x, wid = tid >> 5, lid = tid & 31;
    const int g = lid >> 2, tig = lid & 3;
    const int m0 = blockIdx.y * BM, n0 = blockIdx.x * BN;
    const int rbase = (wid / WCOLS) * (MT * 16);
    const int cgw = wid % WCOLS;
    const int arow = tid >> 2, ak8 = (tid & 3) * 8;
    const float* Wblk = Wf + (size_t)blockIdx.x * NTT * CHUNK;

    if (SCALE)
        for (int i = tid; i < BM * E_; i += 256) coef_s[i] = coef[m0 * E_ + i];
    __syncthreads();

    auto cpB = [&](int t, int buf) {
#pragma unroll
        for (int i = 0; i < BN / 32; i++) {
            int off = tid + 256 * i;
            CP_ASYNC16(sb + offB0 + buf * BBYTES + off * 16, Wblk + t * CHUNK + off * 4);
        }
        CP_COMMIT();
    };
    auto ldA = [&](int t, float4* pa) {
        const int i0 = (t * 32) % IN;
        const float* ap = A + (size_t)(m0 + arow) * lda + i0 + ak8;
        pa[0] = *(const float4*)ap;
        pa[1] = *(const float4*)(ap + 4);
    };
    auto stA = [&](int t, int buf, const float4* pa) {
        float* As = (float*)(smem + offA[buf]);
        float s = 1.f;
        if (SCALE) s = coef_s[arow * E_ + (t * 32) / IN];
#pragma unroll
        for (int a = 0; a < 2; a++) {
            uint4 u;
            const float* pv = (const float*)&pa[a];
            uint32_t* uu = (uint32_t*)&u;
#pragma unroll
            for (int q = 0; q < 4; q++) uu[q] = tf32u(pv[q] * s);
            *(uint4*)(As + arow * ASTR + ak8 + 4 * a) = u;
        }
    };
    auto stSpecA = [&](int buf) {
        float* As = (float*)(smem + offA[buf]);
#pragma unroll
        for (int a = 0; a < 2; a++) {
            uint4 u = {0u, 0u, 0u, 0u};
            uint32_t* uu = (uint32_t*)&u;
#pragma unroll
            for (int q = 0; q < 4; q++) {
                int k = ak8 + 4 * a + q;
                if (SCALE) { if (k < E_) uu[q] = tf32u(coef_s[arow * E_ + k]); }
                else       { if (k == 0) uu[q] = 0x3f800000u; }
            }
            *(uint4*)(As + arow * ASTR + ak8 + 4 * a) = u;
        }
    };

    float acc[MT][4][4] = {};

    cpB(0, 0);
    cpB(1, 1);
    float4 pa[2];
    ldA(0, pa);
    stA(0, 0, pa);
    CP_WAIT1();
    __syncthreads();

    for (int t = 0; t < NTT; t++) {
        const int abuf = t & 1, bbuf = t % 3;
        if (t + 2 < NTT) cpB(t + 2, (t + 2) % 3);
        const bool nxt = (t + 1 < NTT), nrm = (t + 1 < NT);
        if (nxt && nrm) ldA(t + 1, pa);

        {
            const uint32_t* Asu = (const uint32_t*)(smem + offA[abuf]);
            const char* Bbase = smem + offB0 + bbuf * BBYTES;
#pragma unroll
            for (int k8 = 0; k8 < 4; k8++) {
                uint32_t af[MT][4], bf[4][2];
#pragma unroll
                for (int mt = 0; mt < MT; mt++) {
                    const int r0 = rbase + mt * 16 + g;
                    const int kk = k8 * 8 + tig;
                    af[mt][0] = Asu[r0 * ASTR + kk];
                    af[mt][1] = Asu[(r0 + 8) * ASTR + kk];
                    af[mt][2] = Asu[r0 * ASTR + kk + 4];
                    af[mt][3] = Asu[(r0 + 8) * ASTR + kk + 4];
                }
#pragma unroll
                for (int nt = 0; nt < 4; nt++)
                    *(uint2*)bf[nt] = *(const uint2*)(Bbase +
                        ((((cgw * 4 + k8) * 4 + nt) * 64) + lid * 2) * 4);
#pragma unroll
                for (int mt = 0; mt < MT; mt++)
#pragma unroll
                    for (int nt = 0; nt < 4; nt++)
                        MMA_TF32(acc[mt][nt], af[mt], bf[nt]);
            }
        }

        if (nxt) {
            if (nrm) stA(t + 1, abuf ^ 1, pa);
            else     stSpecA(abuf ^ 1);
            if (t + 2 < NTT) CP_WAIT1(); else CP_WAIT0();
            __syncthreads();
        }
    }

#pragma unroll
    for (int mt = 0; mt < MT; mt++) {
        const int r = m0 + rbase + mt * 16 + g;
#pragma unroll
        for (int nt = 0; nt < 4; nt++) {
            const int c = n0 + cgw * 32 + nt * 8 + 2 * tig;
            float2 v0, v1;
            v0.x = acc[mt][nt][0]; v0.y = acc[mt][nt][1];
            v1.x = acc[mt][nt][2]; v1.y = acc[mt][nt][3];
            if (ACT == 1) {
                v0.x = (v0.x > 0.f) ? v0.x : expm1f(v0.x);
                v0.y = (v0.y > 0.f) ? v0.y : expm1f(v0.y);
                v1.x = (v1.x > 0.f) ? v1.x : expm1f(v1.x);
                v1.y = (v1.y > 0.f) ? v1.y : expm1f(v1.y);
            }
            *(float2*)(Cout + (size_t)r * ldc + c)       = v0;
            *(float2*)(Cout + (size_t)(r + 8) * ldc + c) = v1;
        }
    }
}

// ---------------- launch ----------------
extern "C" void kernel_launch(void* const* d_in, const int* in_sizes, int n_in,
                              void* d_out, int out_size)
{
    const float* x   = (const float*)d_in[0];
    const float* z   = (const float*)d_in[1];
    const float* gw0 = (const float*)d_in[2];
    const float* gb0 = (const float*)d_in[3];
    const float* gw1 = (const float*)d_in[4];
    const float* gb1 = (const float*)d_in[5];
    const float* gw2 = (const float*)d_in[6];
    const float* gb2 = (const float*)d_in[7];
    const float* gw3 = (const float*)d_in[8];
    const float* gb3 = (const float*)d_in[9];
    const float* w0  = (const float*)d_in[10];
    const float* b0  = (const float*)d_in[11];
    const float* w1  = (const float*)d_in[12];
    const float* b1  = (const float*)d_in[13];
    const float* w2  = (const float*)d_in[14];
    const float* b2  = (const float*)d_in[15];
    float* out = (float*)d_out;

    float *xz, *g0, *g1, *g2, *h1, *h2, *coef, *f0, *f1, *f2, *fg0, *fg1, *fg2;
    cudaGetSymbolAddress((void**)&xz, g_xz);
    cudaGetSymbolAddress((void**)&g0, g_g0);
    cudaGetSymbolAddress((void**)&g1, g_g1);
    cudaGetSymbolAddress((void**)&g2, g_g2);
    cudaGetSymbolAddress((void**)&h1, g_h1);
    cudaGetSymbolAddress((void**)&h2, g_h2);
    cudaGetSymbolAddress((void**)&coef, g_coef);
    cudaGetSymbolAddress((void**)&f0, g_f0);
    cudaGetSymbolAddress((void**)&f1, g_f1);
    cudaGetSymbolAddress((void**)&f2, g_f2);
    cudaGetSymbolAddress((void**)&fg0, g_fg0);
    cudaGetSymbolAddress((void**)&fg1, g_fg1);
    cudaGetSymbolAddress((void**)&fg2, g_fg2);

    const int SM128 = 2048 + 2 * 9216 + 3 * 16384;  // 69632
    const int SM64  = 2048 + 2 * 9216 + 3 * 8192;   // 45056
    cudaFuncSetAttribute(mma_kernel<0, DIN_,  5, 128, 1>, cudaFuncAttributeMaxDynamicSharedMemorySize, SM128);
    cudaFuncSetAttribute(mma_kernel<0, HG_,   8, 128, 1>, cudaFuncAttributeMaxDynamicSharedMemorySize, SM128);
    cudaFuncSetAttribute(mma_kernel<1, DIN_, 40, 128, 1>, cudaFuncAttributeMaxDynamicSharedMemorySize, SM128);
    cudaFuncSetAttribute(mma_kernel<1, IN1_, 72, 128, 1>, cudaFuncAttributeMaxDynamicSharedMemorySize, SM128);
    cudaFuncSetAttribute(mma_kernel<1, IN1_, 72, 64,  0>, cudaFuncAttributeMaxDynamicSharedMemorySize, SM64);

    pack_kernel<<<592, 256>>>(x, z);
    wprep_kernel<<<296, 256>>>(w0, b0, w1, b1, w2, b2, gw0, gb0, gw1, gb1, gw2, gb2);

    // gating MLP, plain tf32 (launch #5 = g2 mma, profiled)
    mma_kernel<0, DIN_, 5, 128, 1><<<dim3(2, 128), 256, SM128>>>(xz, DIN_, fg0, nullptr, g0, HG_);
    mma_kernel<0, HG_,  8, 128, 1><<<dim3(2, 128), 256, SM128>>>(g0, HG_, fg1, nullptr, g1, HG_);
    mma_kernel<0, HG_,  8, 128, 1><<<dim3(2, 128), 256, SM128>>>(g1, HG_, fg2, nullptr, g2, HG_);
    coef_kernel<<<128, 256>>>(g2, gw3, gb3);

    mma_kernel<1, DIN_, 40, 128, 1><<<dim3(2, 128), 256, SM128>>>(xz, DIN_, f0, coef, h1, IN1_);
    mma_kernel<1, IN1_, 72, 128, 1><<<dim3(2, 128), 256, SM128>>>(h1, IN1_, f1, coef, h2, IN1_);
    mma_kernel<1, IN1_, 72, 64, 0><<<dim3(2, 128), 256, SM64>>>(h2, IN1_, f2, coef, out, NXT_);
}

// round 11
// speedup vs baseline: 1.6682x; 1.3519x over previous
#include <cuda_runtime.h>
#include <cuda_fp16.h>
#include <math.h>
#include <stdint.h>

#define B_     8192
#define OBS_   128
#define LAT_   32
#define NXT_   128
#define E_     8
#define HG_    256
#define H_     256
#define DIN_   (OBS_ + LAT_)   // 160
#define IN1_   (H_ + LAT_)     // 288

typedef unsigned int u32;

// ---------------- device scratch ----------------
__device__ float g_xz [B_ * DIN_];
__device__ float g_g0 [B_ * HG_];
__device__ float g_g1 [B_ * HG_];
__device__ float g_g2 [B_ * HG_];
__device__ float g_h1 [B_ * IN1_];
__device__ float g_h2 [B_ * IN1_];
__device__ float g_coef[B_ * E_];
// fragment-major fp16 weights (bias tile appended as last k-tile), half2-packed words
__device__ u32 g_f0 [2 * 41 * 2048];
__device__ u32 g_f1 [2 * 73 * 2048];
__device__ u32 g_f2 [2 * 73 * 1024];
__device__ u32 g_fg0[2 *  6 * 2048];
__device__ u32 g_fg1[2 *  9 * 2048];
__device__ u32 g_fg2[2 *  9 * 2048];

// ---------------- helpers ----------------
__device__ __forceinline__ uint32_t smem_u32(const void* p) {
    uint32_t a;
    asm("{ .reg .u64 t; cvta.to.shared.u64 t, %1; cvt.u32.u64 %0, t; }" : "=r"(a) : "l"(p));
    return a;
}
#define CP_ASYNC16(dst, src) \
    asm volatile("cp.async.cg.shared.global [%0], [%1], 16;" :: "r"(dst), "l"(src) : "memory")
#define CP_COMMIT() asm volatile("cp.async.commit_group;" ::: "memory")
#define CP_WAIT0()  asm volatile("cp.async.wait_group 0;" ::: "memory")
#define CP_WAIT1()  asm volatile("cp.async.wait_group 1;" ::: "memory")

#define MMA_F16(d, a, b)                                                           \
    asm volatile("mma.sync.aligned.m16n8k16.row.col.f32.f16.f16.f32 "              \
        "{%0,%1,%2,%3}, {%4,%5,%6,%7}, {%8,%9}, {%0,%1,%2,%3};"                    \
        : "+f"((d)[0]), "+f"((d)[1]), "+f"((d)[2]), "+f"((d)[3])                   \
        : "r"((a)[0]), "r"((a)[1]), "r"((a)[2]), "r"((a)[3]),                      \
          "r"((b)[0]), "r"((b)[1]))

__device__ __forceinline__ u32 pack2(float a, float b) {
    __half2 h = __floats2half2_rn(a, b);
    return *(u32*)&h;
}

// ---------------- pack ----------------
__global__ void pack_kernel(const float* __restrict__ x, const float* __restrict__ z)
{
    int stride = gridDim.x * blockDim.x;
    int idx = blockIdx.x * blockDim.x + threadIdx.x;
    for (int t = idx; t < B_ * DIN_; t += stride) {
        int b = t / DIN_, c = t - b * DIN_;
        g_xz[t] = (c < OBS_) ? x[b * OBS_ + c] : z[b * LAT_ + (c - OBS_)];
    }
    for (int t = idx; t < B_ * LAT_; t += stride) {
        int b = t / LAT_, c = t - b * LAT_;
        float v = z[t];
        g_h1[b * IN1_ + H_ + c] = v;
        g_h2[b * IN1_ + H_ + c] = v;
    }
}

// ---------------- fused weight -> fragment-major fp16 ----------------
// Word w within a tile (CHUNKW = BN*16 words):
//   w = ((cg*2 + k16)*4 + nt)*64 + lid*2 + jj
//   k = k16*16 + jj*8 + (lid&3)*2 + h ; col = nblk*BN + cg*32 + nt*8 + (lid>>2)
// Bias tile (t == NT): rows k < NB (NB = E_ experts, 1 gating vector).
__device__ void wfrag_seg(const float* __restrict__ W, const float* __restrict__ bias,
                          u32* __restrict__ dst, int N, int NT, int NB, int BN,
                          int idx, int stride)
{
    const int CHUNKW = BN * 16;
    const int NTT = NT + 1;
    int total = (N / BN) * NTT * CHUNKW;
    for (int i = idx; i < total; i += stride) {
        int nblk = i / (NTT * CHUNKW);
        int r = i - nblk * NTT * CHUNKW;
        int t = r / CHUNKW;
        int w = r - t * CHUNKW;
        int jj  = w & 1;
        int lid = (w >> 1) & 31;
        int grp = w >> 6;
        int nt = grp & 3, k16 = (grp >> 2) & 1, cg = grp >> 3;
        int col = nblk * BN + cg * 32 + nt * 8 + (lid >> 2);
        int k0  = k16 * 16 + jj * 8 + (lid & 3) * 2;
        float v0, v1;
        if (t < NT) {
            v0 = W[(size_t)(t * 32 + k0) * N + col];
            v1 = W[(size_t)(t * 32 + k0 + 1) * N + col];
        } else {
            v0 = (k0     < NB) ? bias[k0 * N + col]       : 0.f;
            v1 = (k0 + 1 < NB) ? bias[(k0 + 1) * N + col] : 0.f;
        }
        dst[i] = pack2(v0, v1);
    }
}
__global__ void wprep_kernel(const float* w0, const float* b0,
                             const float* w1, const float* b1,
                             const float* w2, const float* b2,
                             const float* gw0, const float* gb0,
                             const float* gw1, const float* gb1,
                             const float* gw2, const float* gb2)
{
    int idx = blockIdx.x * blockDim.x + threadIdx.x;
    int stride = gridDim.x * blockDim.x;
    wfrag_seg(w0,  b0,  g_f0,  256, 40, E_, 128, idx, stride);
    wfrag_seg(w1,  b1,  g_f1,  256, 72, E_, 128, idx, stride);
    wfrag_seg(w2,  b2,  g_f2,  128, 72, E_,  64, idx, stride);
    wfrag_seg(gw0, gb0, g_fg0, 256,  5, 1,  128, idx, stride);
    wfrag_seg(gw1, gb1, g_fg1, 256,  8, 1,  128, idx, stride);
    wfrag_seg(gw2, gb2, g_fg2, 256,  8, 1,  128, idx, stride);
}

// ---------------- gating head + softmax (fp32) ----------------
__global__ __launch_bounds__(256)
void coef_kernel(const float* __restrict__ g2,
                 const float* __restrict__ gw3, const float* __restrict__ gb3)
{
    __shared__ float w_s[HG_ * 9];
    for (int i = threadIdx.x; i < HG_ * E_; i += blockDim.x)
        w_s[(i / E_) * 9 + (i % E_)] = gw3[i];
    __syncthreads();
    int lane = threadIdx.x & 31;
    int warp = (blockIdx.x * blockDim.x + threadIdx.x) >> 5;
    int nwarps = (gridDim.x * blockDim.x) >> 5;
    for (int b = warp; b < B_; b += nwarps) {
        float acc[E_] = {};
        for (int i = lane; i < HG_; i += 32) {
            float v = g2[(size_t)b * HG_ + i];
            const float* wr = &w_s[i * 9];
#pragma unroll
            for (int e = 0; e < E_; e++) acc[e] = fmaf(v, wr[e], acc[e]);
        }
#pragma unroll
        for (int e = 0; e < E_; e++)
#pragma unroll
            for (int off = 16; off; off >>= 1)
                acc[e] += __shfl_xor_sync(0xFFFFFFFFu, acc[e], off);
        if (lane == 0) {
            float mx = -1e30f;
#pragma unroll
            for (int e = 0; e < E_; e++) { acc[e] += gb3[e]; mx = fmaxf(mx, acc[e]); }
            float s = 0.f;
#pragma unroll
            for (int e = 0; e < E_; e++) { acc[e] = expf(acc[e] - mx); s += acc[e]; }
            float inv = 1.f / s;
#pragma unroll
            for (int e = 0; e < E_; e++) g_coef[b * E_ + e] = acc[e] * inv;
        }
    }
}

// ---------------- fp16 tensor GEMM: BM=64, frag-major B ----------------
// SCALE 1 (expert): C = act([coef*A | coef] @ [[W];[bias_E]])
// SCALE 0 (plain) : C = act([A | 1] @ [[W];[bias]])
template<int SCALE, int IN, int NT, int BN, int ACT>
__global__ __launch_bounds__(256, 3)
void mma_kernel(const float* __restrict__ A, int lda,
                const u32* __restrict__ Wf,
                const float* __restrict__ coef,
                float* __restrict__ Cout, int ldc)
{
    constexpr int BM = 64, NTT = NT + 1;
    constexpr int ASTRW = 20;                     // A row stride in words (40 halves)
    constexpr int CHUNKW = BN * 16;
    constexpr int ABYTES = BM * ASTRW * 4, BBYTES = CHUNKW * 4;
    constexpr int WCOLS = BN / 32, WROWS = 8 / WCOLS, MT = BM / (WROWS * 16);

    extern __shared__ char smem[];
    float* coef_s = (float*)smem;
    const int offA[2] = {2048, 2048 + ABYTES};
    const int offB0 = 2048 + 2 * ABYTES;
    const uint32_t sb = smem_u32(smem);

    const int tid = threadIdx.x, wid = tid >> 5, lid = tid & 31;
    const int g = lid >> 2, tig = lid & 3;
    const int m0 = blockIdx.y * BM, n0 = blockIdx.x * BN;
    const int rbase = (wid / WCOLS) * (MT * 16);
    const int cgw = wid % WCOLS;
    const int arow = tid >> 2, wq = tid & 3;
    const u32* Wblk = Wf + (size_t)blockIdx.x * NTT * CHUNKW;

    if (SCALE)
        for (int i = tid; i < BM * E_; i += 256) coef_s[i] = coef[m0 * E_ + i];
    __syncthreads();

    auto cpB = [&](int t, int buf) {
#pragma unroll
        for (int i = 0; i < BN / 64; i++) {
            int off = tid + 256 * i;
            CP_ASYNC16(sb + offB0 + buf * BBYTES + off * 16, Wblk + t * CHUNKW + off * 4);
        }
        CP_COMMIT();
    };
    auto ldA = [&](int t, float4* pa) {
        const int i0 = (t * 32) % IN;
        const float* ap = A + (size_t)(m0 + arow) * lda + i0 + wq * 8;
        pa[0] = *(const float4*)ap;
        pa[1] = *(const float4*)(ap + 4);
    };
    auto stA = [&](int t, int buf, const float4* pa) {
        u32* As = (u32*)(smem + offA[buf]);
        float s = 1.f;
        if (SCALE) s = coef_s[arow * E_ + (t * 32) / IN];
        const float* pv = (const float*)pa;
#pragma unroll
        for (int j = 0; j < 4; j++)
            As[arow * ASTRW + wq * 4 + j] = pack2(pv[2*j] * s, pv[2*j+1] * s);
    };
    auto stSpecA = [&](int buf) {
        u32* As = (u32*)(smem + offA[buf]);
#pragma unroll
        for (int j = 0; j < 4; j++) {
            int c0 = wq * 8 + 2 * j;
            float v0 = 0.f, v1 = 0.f;
            if (SCALE) {
                if (c0     < E_) v0 = coef_s[arow * E_ + c0];
                if (c0 + 1 < E_) v1 = coef_s[arow * E_ + c0 + 1];
            } else {
                if (c0 == 0) v0 = 1.f;
            }
            As[arow * ASTRW + wq * 4 + j] = pack2(v0, v1);
        }
    };

    float acc[MT][4][4] = {};

    cpB(0, 0);
    cpB(1, 1);
    float4 pa[2];
    ldA(0, pa);
    stA(0, 0, pa);
    CP_WAIT1();
    __syncthreads();

    for (int t = 0; t < NTT; t++) {
        const int abuf = t & 1, bbuf = t % 3;
        if (t + 2 < NTT) cpB(t + 2, (t + 2) % 3);
        const bool nxt = (t + 1 < NTT), nrm = (t + 1 < NT);
        if (nxt && nrm) ldA(t + 1, pa);

        {
            const u32* Asu = (const u32*)(smem + offA[abuf]);
            const u32* Bw  = (const u32*)(smem + offB0 + bbuf * BBYTES);
#pragma unroll
            for (int k16 = 0; k16 < 2; k16++) {
                u32 af[MT][4], bf[4][2];
#pragma unroll
                for (int mt = 0; mt < MT; mt++) {
                    const int r0 = rbase + mt * 16 + g;
                    const int kb = k16 * 8 + tig;
                    af[mt][0] = Asu[r0 * ASTRW + kb];
                    af[mt][1] = Asu[(r0 + 8) * ASTRW + kb];
                    af[mt][2] = Asu[r0 * ASTRW + kb + 4];
                    af[mt][3] = Asu[(r0 + 8) * ASTRW + kb + 4];
                }
#pragma unroll
                for (int nt = 0; nt < 4; nt++)
                    *(uint2*)bf[nt] = *(const uint2*)(Bw +
                        ((cgw * 2 + k16) * 4 + nt) * 64 + lid * 2);
#pragma unroll
                for (int mt = 0; mt < MT; mt++)
#pragma unroll
                    for (int nt = 0; nt < 4; nt++)
                        MMA_F16(acc[mt][nt], af[mt], bf[nt]);
            }
        }

        if (nxt) {
            if (nrm) stA(t + 1, abuf ^ 1, pa);
            else     stSpecA(abuf ^ 1);
            if (t + 2 < NTT) CP_WAIT1(); else CP_WAIT0();
            __syncthreads();
        }
    }

#pragma unroll
    for (int mt = 0; mt < MT; mt++) {
        const int r = m0 + rbase + mt * 16 + g;
#pragma unroll
        for (int nt = 0; nt < 4; nt++) {
            const int c = n0 + cgw * 32 + nt * 8 + 2 * tig;
            float2 v0, v1;
            v0.x = acc[mt][nt][0]; v0.y = acc[mt][nt][1];
            v1.x = acc[mt][nt][2]; v1.y = acc[mt][nt][3];
            if (ACT == 1) {
                v0.x = (v0.x > 0.f) ? v0.x : expm1f(v0.x);
                v0.y = (v0.y > 0.f) ? v0.y : expm1f(v0.y);
                v1.x = (v1.x > 0.f) ? v1.x : expm1f(v1.x);
                v1.y = (v1.y > 0.f) ? v1.y : expm1f(v1.y);
            }
            *(float2*)(Cout + (size_t)r * ldc + c)       = v0;
            *(float2*)(Cout + (size_t)(r + 8) * ldc + c) = v1;
        }
    }
}

// ---------------- launch ----------------
extern "C" void kernel_launch(void* const* d_in, const int* in_sizes, int n_in,
                              void* d_out, int out_size)
{
    const float* x   = (const float*)d_in[0];
    const float* z   = (const float*)d_in[1];
    const float* gw0 = (const float*)d_in[2];
    const float* gb0 = (const float*)d_in[3];
    const float* gw1 = (const float*)d_in[4];
    const float* gb1 = (const float*)d_in[5];
    const float* gw2 = (const float*)d_in[6];
    const float* gb2 = (const float*)d_in[7];
    const float* gw3 = (const float*)d_in[8];
    const float* gb3 = (const float*)d_in[9];
    const float* w0  = (const float*)d_in[10];
    const float* b0  = (const float*)d_in[11];
    const float* w1  = (const float*)d_in[12];
    const float* b1  = (const float*)d_in[13];
    const float* w2  = (const float*)d_in[14];
    const float* b2  = (const float*)d_in[15];
    float* out = (float*)d_out;

    float *xz, *g0, *g1, *g2, *h1, *h2, *coef;
    u32 *f0, *f1, *f2, *fg0, *fg1, *fg2;
    cudaGetSymbolAddress((void**)&xz, g_xz);
    cudaGetSymbolAddress((void**)&g0, g_g0);
    cudaGetSymbolAddress((void**)&g1, g_g1);
    cudaGetSymbolAddress((void**)&g2, g_g2);
    cudaGetSymbolAddress((void**)&h1, g_h1);
    cudaGetSymbolAddress((void**)&h2, g_h2);
    cudaGetSymbolAddress((void**)&coef, g_coef);
    cudaGetSymbolAddress((void**)&f0, g_f0);
    cudaGetSymbolAddress((void**)&f1, g_f1);
    cudaGetSymbolAddress((void**)&f2, g_f2);
    cudaGetSymbolAddress((void**)&fg0, g_fg0);
    cudaGetSymbolAddress((void**)&fg1, g_fg1);
    cudaGetSymbolAddress((void**)&fg2, g_fg2);

    const int SM128 = 2048 + 2 * (64 * 20 * 4) + 3 * 8192;  // 36864
    const int SM64  = 2048 + 2 * (64 * 20 * 4) + 3 * 4096;  // 24576
    cudaFuncSetAttribute(mma_kernel<0, DIN_,  5, 128, 1>, cudaFuncAttributeMaxDynamicSharedMemorySize, SM128);
    cudaFuncSetAttribute(mma_kernel<0, HG_,   8, 128, 1>, cudaFuncAttributeMaxDynamicSharedMemorySize, SM128);
    cudaFuncSetAttribute(mma_kernel<1, DIN_, 40, 128, 1>, cudaFuncAttributeMaxDynamicSharedMemorySize, SM128);
    cudaFuncSetAttribute(mma_kernel<1, IN1_, 72, 128, 1>, cudaFuncAttributeMaxDynamicSharedMemorySize, SM128);
    cudaFuncSetAttribute(mma_kernel<1, IN1_, 72, 64,  0>, cudaFuncAttributeMaxDynamicSharedMemorySize, SM64);

    pack_kernel<<<592, 256>>>(x, z);
    wprep_kernel<<<296, 256>>>(w0, b0, w1, b1, w2, b2, gw0, gb0, gw1, gb1, gw2, gb2);

    mma_kernel<0, DIN_, 5, 128, 1><<<dim3(2, 128), 256, SM128>>>(xz, DIN_, fg0, nullptr, g0, HG_);
    mma_kernel<0, HG_,  8, 128, 1><<<dim3(2, 128), 256, SM128>>>(g0, HG_, fg1, nullptr, g1, HG_);
    mma_kernel<0, HG_,  8, 128, 1><<<dim3(2, 128), 256, SM128>>>(g1, HG_, fg2, nullptr, g2, HG_);
    coef_kernel<<<128, 256>>>(g2, gw3, gb3);

    mma_kernel<1, DIN_, 40, 128, 1><<<dim3(2, 128), 256, SM128>>>(xz, DIN_, f0, coef, h1, IN1_);
    mma_kernel<1, IN1_, 72, 128, 1><<<dim3(2, 128), 256, SM128>>>(h1, IN1_, f1, coef, h2, IN1_);
    mma_kernel<1, IN1_, 72, 64, 0><<<dim3(2, 128), 256, SM64>>>(h2, IN1_, f2, coef, out, NXT_);
}

// round 12
// speedup vs baseline: 1.6717x; 1.0021x over previous
#include <cuda_runtime.h>
#include <cuda_fp16.h>
#include <math.h>
#include <stdint.h>

#define B_     8192
#define OBS_   128
#define LAT_   32
#define NXT_   128
#define E_     8
#define HG_    256
#define H_     256
#define DIN_   (OBS_ + LAT_)   // 160
#define IN1_   (H_ + LAT_)     // 288

typedef unsigned int u32;

// ---------------- device scratch ----------------
__device__ float g_xz [B_ * DIN_];
__device__ float g_h1 [B_ * IN1_];
__device__ float g_h2 [B_ * IN1_];
__device__ float g_coef[B_ * E_];
// fragment-major fp16 weights (bias tile appended), half2-packed words
__device__ u32 g_f0 [2 * 41 * 2048];
__device__ u32 g_f1 [2 * 73 * 2048];
__device__ u32 g_f2 [2 * 73 * 1024];
__device__ u32 g_fg0[6 * 4096];      // gating, BN=256
__device__ u32 g_fg1[9 * 4096];
__device__ u32 g_fg2[9 * 4096];

// ---------------- helpers ----------------
__device__ __forceinline__ uint32_t smem_u32(const void* p) {
    uint32_t a;
    asm("{ .reg .u64 t; cvta.to.shared.u64 t, %1; cvt.u32.u64 %0, t; }" : "=r"(a) : "l"(p));
    return a;
}
#define CP_ASYNC16(dst, src) \
    asm volatile("cp.async.cg.shared.global [%0], [%1], 16;" :: "r"(dst), "l"(src) : "memory")
#define CP_COMMIT() asm volatile("cp.async.commit_group;" ::: "memory")
#define CP_WAIT0()  asm volatile("cp.async.wait_group 0;" ::: "memory")
#define CP_WAIT1()  asm volatile("cp.async.wait_group 1;" ::: "memory")

#define MMA_F16(d, a, b)                                                           \
    asm volatile("mma.sync.aligned.m16n8k16.row.col.f32.f16.f16.f32 "              \
        "{%0,%1,%2,%3}, {%4,%5,%6,%7}, {%8,%9}, {%0,%1,%2,%3};"                    \
        : "+f"((d)[0]), "+f"((d)[1]), "+f"((d)[2]), "+f"((d)[3])                   \
        : "r"((a)[0]), "r"((a)[1]), "r"((a)[2]), "r"((a)[3]),                      \
          "r"((b)[0]), "r"((b)[1]))

__device__ __forceinline__ u32 pack2(float a, float b) {
    __half2 h = __floats2half2_rn(a, b);
    return *(u32*)&h;
}
__device__ __forceinline__ float elu1(float o) { return (o > 0.f) ? o : expm1f(o); }

// ---------------- pack ----------------
__global__ void pack_kernel(const float* __restrict__ x, const float* __restrict__ z)
{
    int stride = gridDim.x * blockDim.x;
    int idx = blockIdx.x * blockDim.x + threadIdx.x;
    for (int t = idx; t < B_ * DIN_; t += stride) {
        int b = t / DIN_, c = t - b * DIN_;
        g_xz[t] = (c < OBS_) ? x[b * OBS_ + c] : z[b * LAT_ + (c - OBS_)];
    }
    for (int t = idx; t < B_ * LAT_; t += stride) {
        int b = t / LAT_, c = t - b * LAT_;
        float v = z[t];
        g_h1[b * IN1_ + H_ + c] = v;
        g_h2[b * IN1_ + H_ + c] = v;
    }
}

// ---------------- fused weight -> fragment-major fp16 ----------------
// w = ((cg*2 + k16)*4 + nt)*64 + lid*2 + jj ;  k = k16*16 + jj*8 + (lid&3)*2 + h
// col = nblk*BN + cg*32 + nt*8 + (lid>>2).  Bias tile (t==NT): rows k < NB.
__device__ void wfrag_seg(const float* __restrict__ W, const float* __restrict__ bias,
                          u32* __restrict__ dst, int N, int NT, int NB, int BN,
                          int idx, int stride)
{
    const int CHUNKW = BN * 16;
    const int NTT = NT + 1;
    int total = (N / BN) * NTT * CHUNKW;
    for (int i = idx; i < total; i += stride) {
        int nblk = i / (NTT * CHUNKW);
        int r = i - nblk * NTT * CHUNKW;
        int t = r / CHUNKW;
        int w = r - t * CHUNKW;
        int jj  = w & 1;
        int lid = (w >> 1) & 31;
        int grp = w >> 6;
        int nt = grp & 3, k16 = (grp >> 2) & 1, cg = grp >> 3;
        int col = nblk * BN + cg * 32 + nt * 8 + (lid >> 2);
        int k0  = k16 * 16 + jj * 8 + (lid & 3) * 2;
        float v0, v1;
        if (t < NT) {
            v0 = W[(size_t)(t * 32 + k0) * N + col];
            v1 = W[(size_t)(t * 32 + k0 + 1) * N + col];
        } else {
            v0 = (k0     < NB) ? bias[k0 * N + col]       : 0.f;
            v1 = (k0 + 1 < NB) ? bias[(k0 + 1) * N + col] : 0.f;
        }
        dst[i] = pack2(v0, v1);
    }
}
__global__ void wprep_kernel(const float* w0, const float* b0,
                             const float* w1, const float* b1,
                             const float* w2, const float* b2,
                             const float* gw0, const float* gb0,
                             const float* gw1, const float* gb1,
                             const float* gw2, const float* gb2)
{
    int idx = blockIdx.x * blockDim.x + threadIdx.x;
    int stride = gridDim.x * blockDim.x;
    wfrag_seg(w0,  b0,  g_f0,  256, 40, E_, 128, idx, stride);
    wfrag_seg(w1,  b1,  g_f1,  256, 72, E_, 128, idx, stride);
    wfrag_seg(w2,  b2,  g_f2,  128, 72, E_,  64, idx, stride);
    wfrag_seg(gw0, gb0, g_fg0, 256,  5, 1,  256, idx, stride);
    wfrag_seg(gw1, gb1, g_fg1, 256,  8, 1,  256, idx, stride);
    wfrag_seg(gw2, gb2, g_fg2, 256,  8, 1,  256, idx, stride);
}

// ---------------- fused gating MLP + head + softmax ----------------
// One CTA per 64-row block; BN=256 (full width); A resident in smem across layers.
__global__ __launch_bounds__(256, 1)
void gating_kernel(const float* __restrict__ xz,
                   const u32* __restrict__ f0, const u32* __restrict__ f1,
                   const u32* __restrict__ f2,
                   const float* __restrict__ gw3, const float* __restrict__ gb3)
{
    constexpr int AS = 148;                 // A row stride in half2 words
    extern __shared__ char smem[];
    u32* As = (u32*)smem;
    const int offB = 64 * AS * 4;           // 37888; 3 B-buffers of 16KB follow
    const uint32_t sb = smem_u32(smem);

    const int tid = threadIdx.x, wid = tid >> 5, lid = tid & 31;
    const int g = lid >> 2, tig = lid & 3;
    const int m0 = blockIdx.x * 64;
    const int cgw = wid;                    // warp owns cols cgw*32..+31

    // stage layer-0 A (xz fp32 -> fp16) + bias-indicator tile at words 80..95
    for (int i = tid; i < 64 * 96; i += 256) {
        int r = i / 96, w = i - r * 96;
        u32 val;
        if (w < 80) {
            float2 v = *(const float2*)(xz + (size_t)(m0 + r) * DIN_ + 2 * w);
            val = pack2(v.x, v.y);
        } else val = (w == 80) ? pack2(1.f, 0.f) : 0u;
        As[r * AS + w] = val;
    }
    __syncthreads();

    float acc[4][4][4];

    auto run_layer = [&](const u32* Wt, int NTT) {
#pragma unroll
        for (int mt = 0; mt < 4; mt++)
#pragma unroll
            for (int nt = 0; nt < 4; nt++)
#pragma unroll
                for (int q = 0; q < 4; q++) acc[mt][nt][q] = 0.f;
        auto cpB = [&](int t, int buf) {
#pragma unroll
            for (int i = 0; i < 4; i++) {
                int off = tid + 256 * i;
                CP_ASYNC16(sb + offB + buf * 16384 + off * 16, Wt + t * 4096 + off * 4);
            }
            CP_COMMIT();
        };
        cpB(0, 0);
        cpB(1, 1);
        CP_WAIT1();
        __syncthreads();
        for (int t = 0; t < NTT; t++) {
            if (t + 2 < NTT) cpB(t + 2, (t + 2) % 3);
            const u32* Bw = (const u32*)(smem + offB + (t % 3) * 16384);
#pragma unroll
            for (int k16 = 0; k16 < 2; k16++) {
                u32 af[4][4], bf[4][2];
                const int kb = t * 16 + k16 * 8 + tig;
#pragma unroll
                for (int mt = 0; mt < 4; mt++) {
                    const int r0 = mt * 16 + g;
                    af[mt][0] = As[r0 * AS + kb];
                    af[mt][1] = As[(r0 + 8) * AS + kb];
                    af[mt][2] = As[r0 * AS + kb + 4];
                    af[mt][3] = As[(r0 + 8) * AS + kb + 4];
                }
#pragma unroll
                for (int nt = 0; nt < 4; nt++)
                    *(uint2*)bf[nt] = *(const uint2*)(Bw +
                        ((cgw * 2 + k16) * 4 + nt) * 64 + lid * 2);
#pragma unroll
                for (int mt = 0; mt < 4; mt++)
#pragma unroll
                    for (int nt = 0; nt < 4; nt++)
                        MMA_F16(acc[mt][nt], af[mt], bf[nt]);
            }
            if (t + 2 < NTT) CP_WAIT1(); else CP_WAIT0();
            __syncthreads();
        }
    };

    // ELU + write activations back into A buffer (fp16), plus bias tile for next layer
    auto writeback = [&](bool bias_tile) {
#pragma unroll
        for (int mt = 0; mt < 4; mt++) {
            const int r0 = mt * 16 + g;
#pragma unroll
            for (int nt = 0; nt < 4; nt++) {
                const int wv = cgw * 16 + nt * 4 + tig;
                As[r0 * AS + wv]       = pack2(elu1(acc[mt][nt][0]), elu1(acc[mt][nt][1]));
                As[(r0 + 8) * AS + wv] = pack2(elu1(acc[mt][nt][2]), elu1(acc[mt][nt][3]));
            }
        }
        if (bias_tile)
            for (int i = tid; i < 64 * 16; i += 256) {
                int r = i / 16, w = i - r * 16;
                As[r * AS + 128 + w] = (w == 0) ? pack2(1.f, 0.f) : 0u;
            }
        __syncthreads();
    };

    run_layer(f0, 6);  writeback(true);
    run_layer(f1, 9);  writeback(true);
    run_layer(f2, 9);  writeback(false);

    // head: coef = softmax(g2 @ gw3 + gb3); gw3 staged padded (stride 9) in B area
    float* gws = (float*)(smem + offB);
    for (int i = tid; i < 256 * 8; i += 256)
        gws[(i >> 3) * 9 + (i & 7)] = gw3[i];
    __syncthreads();
    {
        const int r = tid >> 2, seg = tid & 3;
        float a[8] = {};
        for (int jj = 0; jj < 32; jj++) {
            const int w = seg + 4 * jj;
            u32 pw = As[r * AS + w];
            float2 v = __half22float2(*(__half2*)&pw);
            const float* wr0 = gws + (2 * w) * 9;
#pragma unroll
            for (int e = 0; e < 8; e++) a[e] += v.x * wr0[e] + v.y * wr0[9 + e];
        }
#pragma unroll
        for (int e = 0; e < 8; e++) {
            a[e] += __shfl_xor_sync(0xFFFFFFFFu, a[e], 1);
            a[e] += __shfl_xor_sync(0xFFFFFFFFu, a[e], 2);
        }
        if (seg == 0) {
            float mx = -1e30f;
#pragma unroll
            for (int e = 0; e < 8; e++) { a[e] += gb3[e]; mx = fmaxf(mx, a[e]); }
            float s = 0.f;
#pragma unroll
            for (int e = 0; e < 8; e++) { a[e] = expf(a[e] - mx); s += a[e]; }
            float inv = 1.f / s;
#pragma unroll
            for (int e = 0; e < 8; e++) g_coef[(m0 + r) * E_ + e] = a[e] * inv;
        }
    }
}

// ---------------- fp16 expert GEMM: BM=64, frag-major B (unchanged from R11) ----------------
template<int SCALE, int IN, int NT, int BN, int ACT>
__global__ __launch_bounds__(256, 3)
void mma_kernel(const float* __restrict__ A, int lda,
                const u32* __restrict__ Wf,
                const float* __restrict__ coef,
                float* __restrict__ Cout, int ldc)
{
    constexpr int BM = 64, NTT = NT + 1;
    constexpr int ASTRW = 20;
    constexpr int CHUNKW = BN * 16;
    constexpr int ABYTES = BM * ASTRW * 4, BBYTES = CHUNKW * 4;
    constexpr int WCOLS = BN / 32, WROWS = 8 / WCOLS, MT = BM / (WROWS * 16);

    extern __shared__ char smem[];
    float* coef_s = (float*)smem;
    const int offA[2] = {2048, 2048 + ABYTES};
    const int offB0 = 2048 + 2 * ABYTES;
    const uint32_t sb = smem_u32(smem);

    const int tid = threadIdx.x, wid = tid >> 5, lid = tid & 31;
    const int g = lid >> 2, tig = lid & 3;
    const int m0 = blockIdx.y * BM, n0 = blockIdx.x * BN;
    const int rbase = (wid / WCOLS) * (MT * 16);
    const int cgw = wid % WCOLS;
    const int arow = tid >> 2, wq = tid & 3;
    const u32* Wblk = Wf + (size_t)blockIdx.x * NTT * CHUNKW;

    if (SCALE)
        for (int i = tid; i < BM * E_; i += 256) coef_s[i] = coef[m0 * E_ + i];
    __syncthreads();

    auto cpB = [&](int t, int buf) {
#pragma unroll
        for (int i = 0; i < BN / 64; i++) {
            int off = tid + 256 * i;
            CP_ASYNC16(sb + offB0 + buf * BBYTES + off * 16, Wblk + t * CHUNKW + off * 4);
        }
        CP_COMMIT();
    };
    auto ldA = [&](int t, float4* pa) {
        const int i0 = (t * 32) % IN;
        const float* ap = A + (size_t)(m0 + arow) * lda + i0 + wq * 8;
        pa[0] = *(const float4*)ap;
        pa[1] = *(const float4*)(ap + 4);
    };
    auto stA = [&](int t, int buf, const float4* pa) {
        u32* As = (u32*)(smem + offA[buf]);
        float s = 1.f;
        if (SCALE) s = coef_s[arow * E_ + (t * 32) / IN];
        const float* pv = (const float*)pa;
#pragma unroll
        for (int j = 0; j < 4; j++)
            As[arow * ASTRW + wq * 4 + j] = pack2(pv[2*j] * s, pv[2*j+1] * s);
    };
    auto stSpecA = [&](int buf) {
        u32* As = (u32*)(smem + offA[buf]);
#pragma unroll
        for (int j = 0; j < 4; j++) {
            int c0 = wq * 8 + 2 * j;
            float v0 = 0.f, v1 = 0.f;
            if (SCALE) {
                if (c0     < E_) v0 = coef_s[arow * E_ + c0];
                if (c0 + 1 < E_) v1 = coef_s[arow * E_ + c0 + 1];
            } else {
                if (c0 == 0) v0 = 1.f;
            }
            As[arow * ASTRW + wq * 4 + j] = pack2(v0, v1);
        }
    };

    float acc[MT][4][4] = {};

    cpB(0, 0);
    cpB(1, 1);
    float4 pa[2];
    ldA(0, pa);
    stA(0, 0, pa);
    CP_WAIT1();
    __syncthreads();

    for (int t = 0; t < NTT; t++) {
        const int abuf = t & 1, bbuf = t % 3;
        if (t + 2 < NTT) cpB(t + 2, (t + 2) % 3);
        const bool nxt = (t + 1 < NTT), nrm = (t + 1 < NT);
        if (nxt && nrm) ldA(t + 1, pa);

        {
            const u32* Asu = (const u32*)(smem + offA[abuf]);
            const u32* Bw  = (const u32*)(smem + offB0 + bbuf * BBYTES);
#pragma unroll
            for (int k16 = 0; k16 < 2; k16++) {
                u32 af[MT][4], bf[4][2];
#pragma unroll
                for (int mt = 0; mt < MT; mt++) {
                    const int r0 = rbase + mt * 16 + g;
                    const int kb = k16 * 8 + tig;
                    af[mt][0] = Asu[r0 * ASTRW + kb];
                    af[mt][1] = Asu[(r0 + 8) * ASTRW + kb];
                    af[mt][2] = Asu[r0 * ASTRW + kb + 4];
                    af[mt][3] = Asu[(r0 + 8) * ASTRW + kb + 4];
                }
#pragma unroll
                for (int nt = 0; nt < 4; nt++)
                    *(uint2*)bf[nt] = *(const uint2*)(Bw +
                        ((cgw * 2 + k16) * 4 + nt) * 64 + lid * 2);
#pragma unroll
                for (int mt = 0; mt < MT; mt++)
#pragma unroll
                    for (int nt = 0; nt < 4; nt++)
                        MMA_F16(acc[mt][nt], af[mt], bf[nt]);
            }
        }

        if (nxt) {
            if (nrm) stA(t + 1, abuf ^ 1, pa);
            else     stSpecA(abuf ^ 1);
            if (t + 2 < NTT) CP_WAIT1(); else CP_WAIT0();
            __syncthreads();
        }
    }

#pragma unroll
    for (int mt = 0; mt < MT; mt++) {
        const int r = m0 + rbase + mt * 16 + g;
#pragma unroll
        for (int nt = 0; nt < 4; nt++) {
            const int c = n0 + cgw * 32 + nt * 8 + 2 * tig;
            float2 v0, v1;
            v0.x = acc[mt][nt][0]; v0.y = acc[mt][nt][1];
            v1.x = acc[mt][nt][2]; v1.y = acc[mt][nt][3];
            if (ACT == 1) {
                v0.x = elu1(v0.x); v0.y = elu1(v0.y);
                v1.x = elu1(v1.x); v1.y = elu1(v1.y);
            }
            *(float2*)(Cout + (size_t)r * ldc + c)       = v0;
            *(float2*)(Cout + (size_t)(r + 8) * ldc + c) = v1;
        }
    }
}

// ---------------- launch ----------------
extern "C" void kernel_launch(void* const* d_in, const int* in_sizes, int n_in,
                              void* d_out, int out_size)
{
    const float* x   = (const float*)d_in[0];
    const float* z   = (const float*)d_in[1];
    const float* gw0 = (const float*)d_in[2];
    const float* gb0 = (const float*)d_in[3];
    const float* gw1 = (const float*)d_in[4];
    const float* gb1 = (const float*)d_in[5];
    const float* gw2 = (const float*)d_in[6];
    const float* gb2 = (const float*)d_in[7];
    const float* gw3 = (const float*)d_in[8];
    const float* gb3 = (const float*)d_in[9];
    const float* w0  = (const float*)d_in[10];
    const float* b0  = (const float*)d_in[11];
    const float* w1  = (const float*)d_in[12];
    const float* b1  = (const float*)d_in[13];
    const float* w2  = (const float*)d_in[14];
    const float* b2  = (const float*)d_in[15];
    float* out = (float*)d_out;

    float *xz, *h1, *h2, *coef;
    u32 *f0, *f1, *f2, *fg0, *fg1, *fg2;
    cudaGetSymbolAddress((void**)&xz, g_xz);
    cudaGetSymbolAddress((void**)&h1, g_h1);
    cudaGetSymbolAddress((void**)&h2, g_h2);
    cudaGetSymbolAddress((void**)&coef, g_coef);
    cudaGetSymbolAddress((void**)&f0, g_f0);
    cudaGetSymbolAddress((void**)&f1, g_f1);
    cudaGetSymbolAddress((void**)&f2, g_f2);
    cudaGetSymbolAddress((void**)&fg0, g_fg0);
    cudaGetSymbolAddress((void**)&fg1, g_fg1);
    cudaGetSymbolAddress((void**)&fg2, g_fg2);

    const int SMG   = 64 * 148 * 4 + 3 * 16384;             // 87040
    const int SM128 = 2048 + 2 * (64 * 20 * 4) + 3 * 8192;  // 36864
    const int SM64  = 2048 + 2 * (64 * 20 * 4) + 3 * 4096;  // 24576
    cudaFuncSetAttribute(gating_kernel, cudaFuncAttributeMaxDynamicSharedMemorySize, SMG);
    cudaFuncSetAttribute(mma_kernel<1, DIN_, 40, 128, 1>, cudaFuncAttributeMaxDynamicSharedMemorySize, SM128);
    cudaFuncSetAttribute(mma_kernel<1, IN1_, 72, 128, 1>, cudaFuncAttributeMaxDynamicSharedMemorySize, SM128);
    cudaFuncSetAttribute(mma_kernel<1, IN1_, 72, 64,  0>, cudaFuncAttributeMaxDynamicSharedMemorySize, SM64);

    pack_kernel<<<592, 256>>>(x, z);
    wprep_kernel<<<296, 256>>>(w0, b0, w1, b1, w2, b2, gw0, gb0, gw1, gb1, gw2, gb2);

    gating_kernel<<<128, 256, SMG>>>(xz, fg0, fg1, fg2, gw3, gb3);

    mma_kernel<1, DIN_, 40, 128, 1><<<dim3(2, 128), 256, SM128>>>(xz, DIN_, f0, coef, h1, IN1_);
    mma_kernel<1, IN1_, 72, 128, 1><<<dim3(2, 128), 256, SM128>>>(h1, IN1_, f1, coef, h2, IN1_);
    mma_kernel<1, IN1_, 72, 64, 0><<<dim3(2, 128), 256, SM64>>>(h2, IN1_, f2, coef, out, NXT_);
}

// round 13
// speedup vs baseline: 2.2258x; 1.3315x over previous
#include <cuda_runtime.h>
#include <cuda_fp16.h>
#include <math.h>
#include <stdint.h>

#define B_     8192
#define OBS_   128
#define LAT_   32
#define NXT_   128
#define E_     8
#define HG_    256
#define H_     256
#define DIN_   (OBS_ + LAT_)   // 160
#define IN1_   (H_ + LAT_)     // 288

typedef unsigned int u32;

// ---------------- device scratch ----------------
__device__ float g_xz [B_ * DIN_];
__device__ float g_h1 [B_ * IN1_];
__device__ float g_h2 [B_ * IN1_];
__device__ float g_coef[B_ * E_];
// fragment-major fp16 weights (bias tile appended), half2-packed words
__device__ u32 g_f0 [2 * 41 * 2048];
__device__ u32 g_f1 [2 * 73 * 2048];
__device__ u32 g_f2 [2 * 73 * 1024];
__device__ u32 g_fg0[6 * 4096];      // gating, BN=256
__device__ u32 g_fg1[9 * 4096];
__device__ u32 g_fg2[9 * 4096];

// ---------------- helpers ----------------
__device__ __forceinline__ uint32_t smem_u32(const void* p) {
    uint32_t a;
    asm("{ .reg .u64 t; cvta.to.shared.u64 t, %1; cvt.u32.u64 %0, t; }" : "=r"(a) : "l"(p));
    return a;
}
#define CP_ASYNC16(dst, src) \
    asm volatile("cp.async.cg.shared.global [%0], [%1], 16;" :: "r"(dst), "l"(src) : "memory")
#define CP_COMMIT() asm volatile("cp.async.commit_group;" ::: "memory")
#define CP_WAIT0()  asm volatile("cp.async.wait_group 0;" ::: "memory")
#define CP_WAIT1()  asm volatile("cp.async.wait_group 1;" ::: "memory")

#define MMA_F16(d, a, b)                                                           \
    asm volatile("mma.sync.aligned.m16n8k16.row.col.f32.f16.f16.f32 "              \
        "{%0,%1,%2,%3}, {%4,%5,%6,%7}, {%8,%9}, {%0,%1,%2,%3};"                    \
        : "+f"((d)[0]), "+f"((d)[1]), "+f"((d)[2]), "+f"((d)[3])                   \
        : "r"((a)[0]), "r"((a)[1]), "r"((a)[2]), "r"((a)[3]),                      \
          "r"((b)[0]), "r"((b)[1]))

__device__ __forceinline__ u32 pack2(float a, float b) {
    __half2 h = __floats2half2_rn(a, b);
    return *(u32*)&h;
}
__device__ __forceinline__ float elu1(float o) { return (o > 0.f) ? o : expm1f(o); }

// ---------------- pack ----------------
__global__ void pack_kernel(const float* __restrict__ x, const float* __restrict__ z)
{
    int stride = gridDim.x * blockDim.x;
    int idx = blockIdx.x * blockDim.x + threadIdx.x;
    for (int t = idx; t < B_ * DIN_; t += stride) {
        int b = t / DIN_, c = t - b * DIN_;
        g_xz[t] = (c < OBS_) ? x[b * OBS_ + c] : z[b * LAT_ + (c - OBS_)];
    }
    for (int t = idx; t < B_ * LAT_; t += stride) {
        int b = t / LAT_, c = t - b * LAT_;
        float v = z[t];
        g_h1[b * IN1_ + H_ + c] = v;
        g_h2[b * IN1_ + H_ + c] = v;
    }
}

// ---------------- fused weight -> fragment-major fp16 ----------------
__device__ void wfrag_seg(const float* __restrict__ W, const float* __restrict__ bias,
                          u32* __restrict__ dst, int N, int NT, int NB, int BN,
                          int idx, int stride)
{
    const int CHUNKW = BN * 16;
    const int NTT = NT + 1;
    int total = (N / BN) * NTT * CHUNKW;
    for (int i = idx; i < total; i += stride) {
        int nblk = i / (NTT * CHUNKW);
        int r = i - nblk * NTT * CHUNKW;
        int t = r / CHUNKW;
        int w = r - t * CHUNKW;
        int jj  = w & 1;
        int lid = (w >> 1) & 31;
        int grp = w >> 6;
        int nt = grp & 3, k16 = (grp >> 2) & 1, cg = grp >> 3;
        int col = nblk * BN + cg * 32 + nt * 8 + (lid >> 2);
        int k0  = k16 * 16 + jj * 8 + (lid & 3) * 2;
        float v0, v1;
        if (t < NT) {
            v0 = W[(size_t)(t * 32 + k0) * N + col];
            v1 = W[(size_t)(t * 32 + k0 + 1) * N + col];
        } else {
            v0 = (k0     < NB) ? bias[k0 * N + col]       : 0.f;
            v1 = (k0 + 1 < NB) ? bias[(k0 + 1) * N + col] : 0.f;
        }
        dst[i] = pack2(v0, v1);
    }
}
__global__ void wprep_kernel(const float* w0, const float* b0,
                             const float* w1, const float* b1,
                             const float* w2, const float* b2,
                             const float* gw0, const float* gb0,
                             const float* gw1, const float* gb1,
                             const float* gw2, const float* gb2)
{
    int idx = blockIdx.x * blockDim.x + threadIdx.x;
    int stride = gridDim.x * blockDim.x;
    wfrag_seg(w0,  b0,  g_f0,  256, 40, E_, 128, idx, stride);
    wfrag_seg(w1,  b1,  g_f1,  256, 72, E_, 128, idx, stride);
    wfrag_seg(w2,  b2,  g_f2,  128, 72, E_,  64, idx, stride);
    wfrag_seg(gw0, gb0, g_fg0, 256,  5, 1,  256, idx, stride);
    wfrag_seg(gw1, gb1, g_fg1, 256,  8, 1,  256, idx, stride);
    wfrag_seg(gw2, gb2, g_fg2, 256,  8, 1,  256, idx, stride);
}

// ---------------- fused gating MLP + head + softmax (unchanged from R12) ----------------
__global__ __launch_bounds__(256, 1)
void gating_kernel(const float* __restrict__ xz,
                   const u32* __restrict__ f0, const u32* __restrict__ f1,
                   const u32* __restrict__ f2,
                   const float* __restrict__ gw3, const float* __restrict__ gb3)
{
    constexpr int AS = 148;
    extern __shared__ char smem[];
    u32* As = (u32*)smem;
    const int offB = 64 * AS * 4;
    const uint32_t sb = smem_u32(smem);

    const int tid = threadIdx.x, wid = tid >> 5, lid = tid & 31;
    const int g = lid >> 2, tig = lid & 3;
    const int m0 = blockIdx.x * 64;
    const int cgw = wid;

    for (int i = tid; i < 64 * 96; i += 256) {
        int r = i / 96, w = i - r * 96;
        u32 val;
        if (w < 80) {
            float2 v = *(const float2*)(xz + (size_t)(m0 + r) * DIN_ + 2 * w);
            val = pack2(v.x, v.y);
        } else val = (w == 80) ? pack2(1.f, 0.f) : 0u;
        As[r * AS + w] = val;
    }
    __syncthreads();

    float acc[4][4][4];

    auto run_layer = [&](const u32* Wt, int NTT) {
#pragma unroll
        for (int mt = 0; mt < 4; mt++)
#pragma unroll
            for (int nt = 0; nt < 4; nt++)
#pragma unroll
                for (int q = 0; q < 4; q++) acc[mt][nt][q] = 0.f;
        auto cpB = [&](int t, int buf) {
#pragma unroll
            for (int i = 0; i < 4; i++) {
                int off = tid + 256 * i;
                CP_ASYNC16(sb + offB + buf * 16384 + off * 16, Wt + t * 4096 + off * 4);
            }
            CP_COMMIT();
        };
        cpB(0, 0);
        cpB(1, 1);
        CP_WAIT1();
        __syncthreads();
        for (int t = 0; t < NTT; t++) {
            if (t + 2 < NTT) cpB(t + 2, (t + 2) % 3);
            const u32* Bw = (const u32*)(smem + offB + (t % 3) * 16384);
#pragma unroll
            for (int k16 = 0; k16 < 2; k16++) {
                u32 af[4][4], bf[4][2];
                const int kb = t * 16 + k16 * 8 + tig;
#pragma unroll
                for (int mt = 0; mt < 4; mt++) {
                    const int r0 = mt * 16 + g;
                    af[mt][0] = As[r0 * AS + kb];
                    af[mt][1] = As[(r0 + 8) * AS + kb];
                    af[mt][2] = As[r0 * AS + kb + 4];
                    af[mt][3] = As[(r0 + 8) * AS + kb + 4];
                }
#pragma unroll
                for (int nt = 0; nt < 4; nt++)
                    *(uint2*)bf[nt] = *(const uint2*)(Bw +
                        ((cgw * 2 + k16) * 4 + nt) * 64 + lid * 2);
#pragma unroll
                for (int mt = 0; mt < 4; mt++)
#pragma unroll
                    for (int nt = 0; nt < 4; nt++)
                        MMA_F16(acc[mt][nt], af[mt], bf[nt]);
            }
            if (t + 2 < NTT) CP_WAIT1(); else CP_WAIT0();
            __syncthreads();
        }
    };

    auto writeback = [&](bool bias_tile) {
#pragma unroll
        for (int mt = 0; mt < 4; mt++) {
            const int r0 = mt * 16 + g;
#pragma unroll
            for (int nt = 0; nt < 4; nt++) {
                const int wv = cgw * 16 + nt * 4 + tig;
                As[r0 * AS + wv]       = pack2(elu1(acc[mt][nt][0]), elu1(acc[mt][nt][1]));
                As[(r0 + 8) * AS + wv] = pack2(elu1(acc[mt][nt][2]), elu1(acc[mt][nt][3]));
            }
        }
        if (bias_tile)
            for (int i = tid; i < 64 * 16; i += 256) {
                int r = i / 16, w = i - r * 16;
                As[r * AS + 128 + w] = (w == 0) ? pack2(1.f, 0.f) : 0u;
            }
        __syncthreads();
    };

    run_layer(f0, 6);  writeback(true);
    run_layer(f1, 9);  writeback(true);
    run_layer(f2, 9);  writeback(false);

    float* gws = (float*)(smem + offB);
    for (int i = tid; i < 256 * 8; i += 256)
        gws[(i >> 3) * 9 + (i & 7)] = gw3[i];
    __syncthreads();
    {
        const int r = tid >> 2, seg = tid & 3;
        float a[8] = {};
        for (int jj = 0; jj < 32; jj++) {
            const int w = seg + 4 * jj;
            u32 pw = As[r * AS + w];
            float2 v = __half22float2(*(__half2*)&pw);
            const float* wr0 = gws + (2 * w) * 9;
#pragma unroll
            for (int e = 0; e < 8; e++) a[e] += v.x * wr0[e] + v.y * wr0[9 + e];
        }
#pragma unroll
        for (int e = 0; e < 8; e++) {
            a[e] += __shfl_xor_sync(0xFFFFFFFFu, a[e], 1);
            a[e] += __shfl_xor_sync(0xFFFFFFFFu, a[e], 2);
        }
        if (seg == 0) {
            float mx = -1e30f;
#pragma unroll
            for (int e = 0; e < 8; e++) { a[e] += gb3[e]; mx = fmaxf(mx, a[e]); }
            float s = 0.f;
#pragma unroll
            for (int e = 0; e < 8; e++) { a[e] = expf(a[e] - mx); s += a[e]; }
            float inv = 1.f / s;
#pragma unroll
            for (int e = 0; e < 8; e++) g_coef[(m0 + r) * E_ + e] = a[e] * inv;
        }
    }
}

// ---------------- expert GEMM v2: A smem-resident, coef folded per expert ----------------
// out = act( sum_e coef_e * (A @ W_e) + coef @ bias )
template<int IN, int TPE, int BN, int ACT>
__global__ __launch_bounds__(256, 2)
void expert_kernel(const float* __restrict__ A, int lda,
                   const u32* __restrict__ Wf,
                   const float* __restrict__ coef,
                   float* __restrict__ Cout, int ldc)
{
    constexpr int NT = E_ * TPE, NTT = NT + 1;
    constexpr int AW = IN / 2, AS = AW + 4;
    constexpr int CHUNKW = BN * 16, BBYTES = CHUNKW * 4;
    constexpr int WCOLS = BN / 32, WROWS = 8 / WCOLS, MT = 64 / (WROWS * 16);

    extern __shared__ char smem[];
    float* coef_s = (float*)smem;               // 64*8 floats = 2KB
    u32* As = (u32*)(smem + 2048);              // 64 x AS words, resident
    const int offB = 2048 + 64 * AS * 4;        // 3-stage B ring
    const uint32_t sb = smem_u32(smem);

    const int tid = threadIdx.x, wid = tid >> 5, lid = tid & 31;
    const int g = lid >> 2, tig = lid & 3;
    const int m0 = blockIdx.y * 64;
    const int rbase = (wid / WCOLS) * (MT * 16);
    const int cgw = wid % WCOLS;
    const u32* Wblk = Wf + (size_t)blockIdx.x * NTT * CHUNKW;

    for (int i = tid; i < 64 * E_; i += 256) coef_s[i] = coef[m0 * E_ + i];
    for (int i = tid; i < 64 * AW; i += 256) {
        int r = i / AW, w = i - r * AW;
        float2 v = *(const float2*)(A + (size_t)(m0 + r) * lda + 2 * w);
        As[r * AS + w] = pack2(v.x, v.y);
    }

    auto cpB = [&](int t, int buf) {
#pragma unroll
        for (int i = 0; i < BN / 64; i++) {
            int off = tid + 256 * i;
            CP_ASYNC16(sb + offB + buf * BBYTES + off * 16, Wblk + t * CHUNKW + off * 4);
        }
        CP_COMMIT();
    };

    cpB(0, 0);
    cpB(1, 1);
    CP_WAIT1();
    __syncthreads();

    float acc[MT][4][4] = {};

    for (int e = 0; e < E_; e++) {
        float pacc[MT][4][4] = {};
#pragma unroll
        for (int s = 0; s < TPE; s++) {
            const int t = e * TPE + s;
            if (t + 2 < NTT) cpB(t + 2, (t + 2) % 3);
            const u32* Bw = (const u32*)(smem + offB + (t % 3) * BBYTES);
#pragma unroll
            for (int k16 = 0; k16 < 2; k16++) {
                const int kw = s * 16 + k16 * 8 + tig;
                u32 af[MT][4], bf[4][2];
#pragma unroll
                for (int mt = 0; mt < MT; mt++) {
                    const int r0 = rbase + mt * 16 + g;
                    af[mt][0] = As[r0 * AS + kw];
                    af[mt][1] = As[(r0 + 8) * AS + kw];
                    af[mt][2] = As[r0 * AS + kw + 4];
                    af[mt][3] = As[(r0 + 8) * AS + kw + 4];
                }
#pragma unroll
                for (int nt = 0; nt < 4; nt++)
                    *(uint2*)bf[nt] = *(const uint2*)(Bw +
                        ((cgw * 2 + k16) * 4 + nt) * 64 + lid * 2);
#pragma unroll
                for (int mt = 0; mt < MT; mt++)
#pragma unroll
                    for (int nt = 0; nt < 4; nt++)
                        MMA_F16(pacc[mt][nt], af[mt], bf[nt]);
            }
            if (t + 1 < NTT) {
                if (t + 2 < NTT) CP_WAIT1(); else CP_WAIT0();
                __syncthreads();
            }
        }
        // fold coef_e (fp32) into acc
#pragma unroll
        for (int mt = 0; mt < MT; mt++) {
            const int r0 = rbase + mt * 16 + g;
            float cf0 = coef_s[r0 * E_ + e], cf1 = coef_s[(r0 + 8) * E_ + e];
#pragma unroll
            for (int nt = 0; nt < 4; nt++) {
                acc[mt][nt][0] = fmaf(cf0, pacc[mt][nt][0], acc[mt][nt][0]);
                acc[mt][nt][1] = fmaf(cf0, pacc[mt][nt][1], acc[mt][nt][1]);
                acc[mt][nt][2] = fmaf(cf1, pacc[mt][nt][2], acc[mt][nt][2]);
                acc[mt][nt][3] = fmaf(cf1, pacc[mt][nt][3], acc[mt][nt][3]);
            }
        }
    }

    // bias tile (t = NT): A-side fragments built from coef in registers
    {
        const u32* Bw = (const u32*)(smem + offB + (NT % 3) * BBYTES);
        u32 af[MT][4], bf[4][2];
#pragma unroll
        for (int mt = 0; mt < MT; mt++) {
            const int r0 = rbase + mt * 16 + g;
            af[mt][0] = pack2(coef_s[r0 * E_ + 2 * tig], coef_s[r0 * E_ + 2 * tig + 1]);
            af[mt][1] = pack2(coef_s[(r0 + 8) * E_ + 2 * tig], coef_s[(r0 + 8) * E_ + 2 * tig + 1]);
            af[mt][2] = 0u;
            af[mt][3] = 0u;
        }
#pragma unroll
        for (int nt = 0; nt < 4; nt++)
            *(uint2*)bf[nt] = *(const uint2*)(Bw + (cgw * 2 * 4 + nt) * 64 + lid * 2);
#pragma unroll
        for (int mt = 0; mt < MT; mt++)
#pragma unroll
            for (int nt = 0; nt < 4; nt++)
                MMA_F16(acc[mt][nt], af[mt], bf[nt]);
    }

    // epilogue
    const int n0 = blockIdx.x * BN;
#pragma unroll
    for (int mt = 0; mt < MT; mt++) {
        const int r = m0 + rbase + mt * 16 + g;
#pragma unroll
        for (int nt = 0; nt < 4; nt++) {
            const int c = n0 + cgw * 32 + nt * 8 + 2 * tig;
            float2 v0, v1;
            v0.x = acc[mt][nt][0]; v0.y = acc[mt][nt][1];
            v1.x = acc[mt][nt][2]; v1.y = acc[mt][nt][3];
            if (ACT == 1) {
                v0.x = elu1(v0.x); v0.y = elu1(v0.y);
                v1.x = elu1(v1.x); v1.y = elu1(v1.y);
            }
            *(float2*)(Cout + (size_t)r * ldc + c)       = v0;
            *(float2*)(Cout + (size_t)(r + 8) * ldc + c) = v1;
        }
    }
}

// ---------------- launch ----------------
extern "C" void kernel_launch(void* const* d_in, const int* in_sizes, int n_in,
                              void* d_out, int out_size)
{
    const float* x   = (const float*)d_in[0];
    const float* z   = (const float*)d_in[1];
    const float* gw0 = (const float*)d_in[2];
    const float* gb0 = (const float*)d_in[3];
    const float* gw1 = (const float*)d_in[4];
    const float* gb1 = (const float*)d_in[5];
    const float* gw2 = (const float*)d_in[6];
    const float* gb2 = (const float*)d_in[7];
    const float* gw3 = (const float*)d_in[8];
    const float* gb3 = (const float*)d_in[9];
    const float* w0  = (const float*)d_in[10];
    const float* b0  = (const float*)d_in[11];
    const float* w1  = (const float*)d_in[12];
    const float* b1  = (const float*)d_in[13];
    const float* w2  = (const float*)d_in[14];
    const float* b2  = (const float*)d_in[15];
    float* out = (float*)d_out;

    float *xz, *h1, *h2, *coef;
    u32 *f0, *f1, *f2, *fg0, *fg1, *fg2;
    cudaGetSymbolAddress((void**)&xz, g_xz);
    cudaGetSymbolAddress((void**)&h1, g_h1);
    cudaGetSymbolAddress((void**)&h2, g_h2);
    cudaGetSymbolAddress((void**)&coef, g_coef);
    cudaGetSymbolAddress((void**)&f0, g_f0);
    cudaGetSymbolAddress((void**)&f1, g_f1);
    cudaGetSymbolAddress((void**)&f2, g_f2);
    cudaGetSymbolAddress((void**)&fg0, g_fg0);
    cudaGetSymbolAddress((void**)&fg1, g_fg1);
    cudaGetSymbolAddress((void**)&fg2, g_fg2);

    const int SMG = 64 * 148 * 4 + 3 * 16384;            // 87040
    const int SM0 = 2048 + 64 * 84 * 4 + 3 * 8192;       // 48128
    const int SM1 = 2048 + 64 * 148 * 4 + 3 * 8192;      // 64512
    const int SM2 = 2048 + 64 * 148 * 4 + 3 * 4096;      // 52224
    cudaFuncSetAttribute(gating_kernel, cudaFuncAttributeMaxDynamicSharedMemorySize, SMG);
    cudaFuncSetAttribute(expert_kernel<DIN_, 5, 128, 1>, cudaFuncAttributeMaxDynamicSharedMemorySize, SM0);
    cudaFuncSetAttribute(expert_kernel<IN1_, 9, 128, 1>, cudaFuncAttributeMaxDynamicSharedMemorySize, SM1);
    cudaFuncSetAttribute(expert_kernel<IN1_, 9, 64,  0>, cudaFuncAttributeMaxDynamicSharedMemorySize, SM2);

    pack_kernel<<<592, 256>>>(x, z);
    wprep_kernel<<<296, 256>>>(w0, b0, w1, b1, w2, b2, gw0, gb0, gw1, gb1, gw2, gb2);

    gating_kernel<<<128, 256, SMG>>>(xz, fg0, fg1, fg2, gw3, gb3);

    expert_kernel<DIN_, 5, 128, 1><<<dim3(2, 128), 256, SM0>>>(xz, DIN_, f0, coef, h1, IN1_);
    expert_kernel<IN1_, 9, 128, 1><<<dim3(2, 128), 256, SM1>>>(h1, IN1_, f1, coef, h2, IN1_);
    expert_kernel<IN1_, 9, 64,  0><<<dim3(2, 128), 256, SM2>>>(h2, IN1_, f2, coef, out, NXT_);
}

// round 14
// speedup vs baseline: 2.3529x; 1.0571x over previous
#include <cuda_runtime.h>
#include <cuda_fp16.h>
#include <math.h>
#include <stdint.h>

#define B_     8192
#define OBS_   128
#define LAT_   32
#define NXT_   128
#define E_     8
#define HG_    256
#define H_     256
#define DIN_   (OBS_ + LAT_)   // 160
#define IN1_   (H_ + LAT_)     // 288

typedef unsigned int u32;

// ---------------- device scratch ----------------
__device__ float g_xz [B_ * DIN_];
__device__ float g_h1 [B_ * IN1_];
__device__ float g_h2 [B_ * IN1_];
__device__ float g_coef[B_ * E_];
// fragment-major fp16 weights (bias tile appended), half2-packed words
__device__ u32 g_f0 [2 * 41 * 2048];
__device__ u32 g_f1 [2 * 73 * 2048];
__device__ u32 g_f2 [2 * 73 * 1024];
__device__ u32 g_fg0[6 * 4096];      // gating, BN=256
__device__ u32 g_fg1[9 * 4096];
__device__ u32 g_fg2[9 * 4096];

// ---------------- helpers ----------------
__device__ __forceinline__ uint32_t smem_u32(const void* p) {
    uint32_t a;
    asm("{ .reg .u64 t; cvta.to.shared.u64 t, %1; cvt.u32.u64 %0, t; }" : "=r"(a) : "l"(p));
    return a;
}
#define CP_ASYNC16(dst, src) \
    asm volatile("cp.async.cg.shared.global [%0], [%1], 16;" :: "r"(dst), "l"(src) : "memory")
#define CP_COMMIT() asm volatile("cp.async.commit_group;" ::: "memory")
#define CP_WAIT0()  asm volatile("cp.async.wait_group 0;" ::: "memory")
#define CP_WAIT1()  asm volatile("cp.async.wait_group 1;" ::: "memory")

#define MMA_F16(d, a, b)                                                           \
    asm volatile("mma.sync.aligned.m16n8k16.row.col.f32.f16.f16.f32 "              \
        "{%0,%1,%2,%3}, {%4,%5,%6,%7}, {%8,%9}, {%0,%1,%2,%3};"                    \
        : "+f"((d)[0]), "+f"((d)[1]), "+f"((d)[2]), "+f"((d)[3])                   \
        : "r"((a)[0]), "r"((a)[1]), "r"((a)[2]), "r"((a)[3]),                      \
          "r"((b)[0]), "r"((b)[1]))

#define LDSM_X4(r, addr)                                                           \
    asm volatile("ldmatrix.sync.aligned.m8n8.x4.shared.b16 {%0,%1,%2,%3}, [%4];"   \
        : "=r"((r)[0]), "=r"((r)[1]), "=r"((r)[2]), "=r"((r)[3]) : "r"(addr))

__device__ __forceinline__ u32 pack2(float a, float b) {
    __half2 h = __floats2half2_rn(a, b);
    return *(u32*)&h;
}
__device__ __forceinline__ float elu1(float o) { return (o > 0.f) ? o : expm1f(o); }

// ---------------- pack ----------------
__global__ void pack_kernel(const float* __restrict__ x, const float* __restrict__ z)
{
    int stride = gridDim.x * blockDim.x;
    int idx = blockIdx.x * blockDim.x + threadIdx.x;
    for (int t = idx; t < B_ * DIN_; t += stride) {
        int b = t / DIN_, c = t - b * DIN_;
        g_xz[t] = (c < OBS_) ? x[b * OBS_ + c] : z[b * LAT_ + (c - OBS_)];
    }
    for (int t = idx; t < B_ * LAT_; t += stride) {
        int b = t / LAT_, c = t - b * LAT_;
        float v = z[t];
        g_h1[b * IN1_ + H_ + c] = v;
        g_h2[b * IN1_ + H_ + c] = v;
    }
}

// ---------------- fused weight -> fragment-major fp16 ----------------
__device__ void wfrag_seg(const float* __restrict__ W, const float* __restrict__ bias,
                          u32* __restrict__ dst, int N, int NT, int NB, int BN,
                          int idx, int stride)
{
    const int CHUNKW = BN * 16;
    const int NTT = NT + 1;
    int total = (N / BN) * NTT * CHUNKW;
    for (int i = idx; i < total; i += stride) {
        int nblk = i / (NTT * CHUNKW);
        int r = i - nblk * NTT * CHUNKW;
        int t = r / CHUNKW;
        int w = r - t * CHUNKW;
        int jj  = w & 1;
        int lid = (w >> 1) & 31;
        int grp = w >> 6;
        int nt = grp & 3, k16 = (grp >> 2) & 1, cg = grp >> 3;
        int col = nblk * BN + cg * 32 + nt * 8 + (lid >> 2);
        int k0  = k16 * 16 + jj * 8 + (lid & 3) * 2;
        float v0, v1;
        if (t < NT) {
            v0 = W[(size_t)(t * 32 + k0) * N + col];
            v1 = W[(size_t)(t * 32 + k0 + 1) * N + col];
        } else {
            v0 = (k0     < NB) ? bias[k0 * N + col]       : 0.f;
            v1 = (k0 + 1 < NB) ? bias[(k0 + 1) * N + col] : 0.f;
        }
        dst[i] = pack2(v0, v1);
    }
}
__global__ void wprep_kernel(const float* w0, const float* b0,
                             const float* w1, const float* b1,
                             const float* w2, const float* b2,
                             const float* gw0, const float* gb0,
                             const float* gw1, const float* gb1,
                             const float* gw2, const float* gb2)
{
    int idx = blockIdx.x * blockDim.x + threadIdx.x;
    int stride = gridDim.x * blockDim.x;
    wfrag_seg(w0,  b0,  g_f0,  256, 40, E_, 128, idx, stride);
    wfrag_seg(w1,  b1,  g_f1,  256, 72, E_, 128, idx, stride);
    wfrag_seg(w2,  b2,  g_f2,  128, 72, E_,  64, idx, stride);
    wfrag_seg(gw0, gb0, g_fg0, 256,  5, 1,  256, idx, stride);
    wfrag_seg(gw1, gb1, g_fg1, 256,  8, 1,  256, idx, stride);
    wfrag_seg(gw2, gb2, g_fg2, 256,  8, 1,  256, idx, stride);
}

// ---------------- fused gating MLP + head + softmax ----------------
__global__ __launch_bounds__(256, 1)
void gating_kernel(const float* __restrict__ xz,
                   const u32* __restrict__ f0, const u32* __restrict__ f1,
                   const u32* __restrict__ f2,
                   const float* __restrict__ gw3, const float* __restrict__ gb3)
{
    constexpr int AS = 148;
    extern __shared__ char smem[];
    u32* As = (u32*)smem;
    const int offB = 64 * AS * 4;
    const uint32_t sb = smem_u32(smem);

    const int tid = threadIdx.x, wid = tid >> 5, lid = tid & 31;
    const int g = lid >> 2, tig = lid & 3;
    const int m0 = blockIdx.x * 64;
    const int cgw = wid;
    // ldmatrix per-lane base: row = ((lid>>3)&1)*8 + (lid&7), word += (lid>>4)*4
    const uint32_t abase = sb + (((((lid >> 3) & 1) * 8 + (lid & 7)) * AS + (lid >> 4) * 4) << 2);

    for (int i = tid; i < 64 * 96; i += 256) {
        int r = i / 96, w = i - r * 96;
        u32 val;
        if (w < 80) {
            float2 v = *(const float2*)(xz + (size_t)(m0 + r) * DIN_ + 2 * w);
            val = pack2(v.x, v.y);
        } else val = (w == 80) ? pack2(1.f, 0.f) : 0u;
        As[r * AS + w] = val;
    }
    __syncthreads();

    float acc[4][4][4];

    auto run_layer = [&](const u32* Wt, int NTT) {
#pragma unroll
        for (int mt = 0; mt < 4; mt++)
#pragma unroll
            for (int nt = 0; nt < 4; nt++)
#pragma unroll
                for (int q = 0; q < 4; q++) acc[mt][nt][q] = 0.f;
        auto cpB = [&](int t, int buf) {
#pragma unroll
            for (int i = 0; i < 4; i++) {
                int off = tid + 256 * i;
                CP_ASYNC16(sb + offB + buf * 16384 + off * 16, Wt + t * 4096 + off * 4);
            }
            CP_COMMIT();
        };
        cpB(0, 0);
        cpB(1, 1);
        CP_WAIT1();
        __syncthreads();
        for (int t = 0; t < NTT; t++) {
            if (t + 2 < NTT) cpB(t + 2, (t + 2) % 3);
            const u32* Bw = (const u32*)(smem + offB + (t % 3) * 16384);
#pragma unroll
            for (int k16 = 0; k16 < 2; k16++) {
                u32 af[4][4], bf[4][2];
                const uint32_t koff = (t * 16 + k16 * 8) << 2;
#pragma unroll
                for (int mt = 0; mt < 4; mt++)
                    LDSM_X4(af[mt], abase + mt * 16 * AS * 4 + koff);
#pragma unroll
                for (int nt = 0; nt < 4; nt++)
                    *(uint2*)bf[nt] = *(const uint2*)(Bw +
                        ((cgw * 2 + k16) * 4 + nt) * 64 + lid * 2);
#pragma unroll
                for (int mt = 0; mt < 4; mt++)
#pragma unroll
                    for (int nt = 0; nt < 4; nt++)
                        MMA_F16(acc[mt][nt], af[mt], bf[nt]);
            }
            if (t + 2 < NTT) CP_WAIT1(); else CP_WAIT0();
            __syncthreads();
        }
    };

    auto writeback = [&](bool bias_tile) {
#pragma unroll
        for (int mt = 0; mt < 4; mt++) {
            const int r0 = mt * 16 + g;
#pragma unroll
            for (int nt = 0; nt < 4; nt++) {
                const int wv = cgw * 16 + nt * 4 + tig;
                As[r0 * AS + wv]       = pack2(elu1(acc[mt][nt][0]), elu1(acc[mt][nt][1]));
                As[(r0 + 8) * AS + wv] = pack2(elu1(acc[mt][nt][2]), elu1(acc[mt][nt][3]));
            }
        }
        if (bias_tile)
            for (int i = tid; i < 64 * 16; i += 256) {
                int r = i / 16, w = i - r * 16;
                As[r * AS + 128 + w] = (w == 0) ? pack2(1.f, 0.f) : 0u;
            }
        __syncthreads();
    };

    run_layer(f0, 6);  writeback(true);
    run_layer(f1, 9);  writeback(true);
    run_layer(f2, 9);  writeback(false);

    float* gws = (float*)(smem + offB);
    for (int i = tid; i < 256 * 8; i += 256)
        gws[(i >> 3) * 9 + (i & 7)] = gw3[i];
    __syncthreads();
    {
        const int r = tid >> 2, seg = tid & 3;
        float a[8] = {};
        for (int jj = 0; jj < 32; jj++) {
            const int w = seg + 4 * jj;
            u32 pw = As[r * AS + w];
            float2 v = __half22float2(*(__half2*)&pw);
            const float* wr0 = gws + (2 * w) * 9;
#pragma unroll
            for (int e = 0; e < 8; e++) a[e] += v.x * wr0[e] + v.y * wr0[9 + e];
        }
#pragma unroll
        for (int e = 0; e < 8; e++) {
            a[e] += __shfl_xor_sync(0xFFFFFFFFu, a[e], 1);
            a[e] += __shfl_xor_sync(0xFFFFFFFFu, a[e], 2);
        }
        if (seg == 0) {
            float mx = -1e30f;
#pragma unroll
            for (int e = 0; e < 8; e++) { a[e] += gb3[e]; mx = fmaxf(mx, a[e]); }
            float s = 0.f;
#pragma unroll
            for (int e = 0; e < 8; e++) { a[e] = expf(a[e] - mx); s += a[e]; }
            float inv = 1.f / s;
#pragma unroll
            for (int e = 0; e < 8; e++) g_coef[(m0 + r) * E_ + e] = a[e] * inv;
        }
    }
}

// ---------------- expert GEMM: A smem-resident + ldmatrix, coef folded per expert ----------------
template<int IN, int TPE, int BN, int ACT>
__global__ __launch_bounds__(256, 2)
void expert_kernel(const float* __restrict__ A, int lda,
                   const u32* __restrict__ Wf,
                   const float* __restrict__ coef,
                   float* __restrict__ Cout, int ldc)
{
    constexpr int NT = E_ * TPE, NTT = NT + 1;
    constexpr int AW = IN / 2, AS = AW + 4;
    constexpr int CHUNKW = BN * 16, BBYTES = CHUNKW * 4;
    constexpr int WCOLS = BN / 32, WROWS = 8 / WCOLS, MT = 64 / (WROWS * 16);

    extern __shared__ char smem[];
    float* coef_s = (float*)smem;
    u32* As = (u32*)(smem + 2048);
    const int offB = 2048 + 64 * AS * 4;
    const uint32_t sb = smem_u32(smem);

    const int tid = threadIdx.x, wid = tid >> 5, lid = tid & 31;
    const int g = lid >> 2, tig = lid & 3;
    const int m0 = blockIdx.y * 64;
    const int rbase = (wid / WCOLS) * (MT * 16);
    const int cgw = wid % WCOLS;
    const u32* Wblk = Wf + (size_t)blockIdx.x * NTT * CHUNKW;
    // ldmatrix per-lane base address
    const uint32_t abase = sb + 2048 +
        (((rbase + ((lid >> 3) & 1) * 8 + (lid & 7)) * AS + (lid >> 4) * 4) << 2);

    for (int i = tid; i < 64 * E_; i += 256) coef_s[i] = coef[m0 * E_ + i];
    for (int i = tid; i < 64 * AW; i += 256) {
        int r = i / AW, w = i - r * AW;
        float2 v = *(const float2*)(A + (size_t)(m0 + r) * lda + 2 * w);
        As[r * AS + w] = pack2(v.x, v.y);
    }

    auto cpB = [&](int t, int buf) {
#pragma unroll
        for (int i = 0; i < BN / 64; i++) {
            int off = tid + 256 * i;
            CP_ASYNC16(sb + offB + buf * BBYTES + off * 16, Wblk + t * CHUNKW + off * 4);
        }
        CP_COMMIT();
    };

    cpB(0, 0);
    cpB(1, 1);
    CP_WAIT1();
    __syncthreads();

    float acc[MT][4][4] = {};

    for (int e = 0; e < E_; e++) {
        float pacc[MT][4][4] = {};
#pragma unroll
        for (int s = 0; s < TPE; s++) {
            const int t = e * TPE + s;
            if (t + 2 < NTT) cpB(t + 2, (t + 2) % 3);
            const u32* Bw = (const u32*)(smem + offB + (t % 3) * BBYTES);
#pragma unroll
            for (int k16 = 0; k16 < 2; k16++) {
                const uint32_t koff = (s * 16 + k16 * 8) << 2;
                u32 af[MT][4], bf[4][2];
#pragma unroll
                for (int mt = 0; mt < MT; mt++)
                    LDSM_X4(af[mt], abase + mt * 16 * AS * 4 + koff);
#pragma unroll
                for (int nt = 0; nt < 4; nt++)
                    *(uint2*)bf[nt] = *(const uint2*)(Bw +
                        ((cgw * 2 + k16) * 4 + nt) * 64 + lid * 2);
#pragma unroll
                for (int mt = 0; mt < MT; mt++)
#pragma unroll
                    for (int nt = 0; nt < 4; nt++)
                        MMA_F16(pacc[mt][nt], af[mt], bf[nt]);
            }
            if (t + 1 < NTT) {
                if (t + 2 < NTT) CP_WAIT1(); else CP_WAIT0();
                __syncthreads();
            }
        }
#pragma unroll
        for (int mt = 0; mt < MT; mt++) {
            const int r0 = rbase + mt * 16 + g;
            float cf0 = coef_s[r0 * E_ + e], cf1 = coef_s[(r0 + 8) * E_ + e];
#pragma unroll
            for (int nt = 0; nt < 4; nt++) {
                acc[mt][nt][0] = fmaf(cf0, pacc[mt][nt][0], acc[mt][nt][0]);
                acc[mt][nt][1] = fmaf(cf0, pacc[mt][nt][1], acc[mt][nt][1]);
                acc[mt][nt][2] = fmaf(cf1, pacc[mt][nt][2], acc[mt][nt][2]);
                acc[mt][nt][3] = fmaf(cf1, pacc[mt][nt][3], acc[mt][nt][3]);
            }
        }
    }

    // bias tile: A-side fragments built from coef in registers
    {
        const u32* Bw = (const u32*)(smem + offB + (NT % 3) * BBYTES);
        u32 af[MT][4], bf[4][2];
#pragma unroll
        for (int mt = 0; mt < MT; mt++) {
            const int r0 = rbase + mt * 16 + g;
            af[mt][0] = pack2(coef_s[r0 * E_ + 2 * tig], coef_s[r0 * E_ + 2 * tig + 1]);
            af[mt][1] = pack2(coef_s[(r0 + 8) * E_ + 2 * tig], coef_s[(r0 + 8) * E_ + 2 * tig + 1]);
            af[mt][2] = 0u;
            af[mt][3] = 0u;
        }
#pragma unroll
        for (int nt = 0; nt < 4; nt++)
            *(uint2*)bf[nt] = *(const uint2*)(Bw + (cgw * 2 * 4 + nt) * 64 + lid * 2);
#pragma unroll
        for (int mt = 0; mt < MT; mt++)
#pragma unroll
            for (int nt = 0; nt < 4; nt++)
                MMA_F16(acc[mt][nt], af[mt], bf[nt]);
    }

    const int n0 = blockIdx.x * BN;
#pragma unroll
    for (int mt = 0; mt < MT; mt++) {
        const int r = m0 + rbase + mt * 16 + g;
#pragma unroll
        for (int nt = 0; nt < 4; nt++) {
            const int c = n0 + cgw * 32 + nt * 8 + 2 * tig;
            float2 v0, v1;
            v0.x = acc[mt][nt][0]; v0.y = acc[mt][nt][1];
            v1.x = acc[mt][nt][2]; v1.y = acc[mt][nt][3];
            if (ACT == 1) {
                v0.x = elu1(v0.x); v0.y = elu1(v0.y);
                v1.x = elu1(v1.x); v1.y = elu1(v1.y);
            }
            *(float2*)(Cout + (size_t)r * ldc + c)       = v0;
            *(float2*)(Cout + (size_t)(r + 8) * ldc + c) = v1;
        }
    }
}

// ---------------- launch ----------------
extern "C" void kernel_launch(void* const* d_in, const int* in_sizes, int n_in,
                              void* d_out, int out_size)
{
    const float* x   = (const float*)d_in[0];
    const float* z   = (const float*)d_in[1];
    const float* gw0 = (const float*)d_in[2];
    const float* gb0 = (const float*)d_in[3];
    const float* gw1 = (const float*)d_in[4];
    const float* gb1 = (const float*)d_in[5];
    const float* gw2 = (const float*)d_in[6];
    const float* gb2 = (const float*)d_in[7];
    const float* gw3 = (const float*)d_in[8];
    const float* gb3 = (const float*)d_in[9];
    const float* w0  = (const float*)d_in[10];
    const float* b0  = (const float*)d_in[11];
    const float* w1  = (const float*)d_in[12];
    const float* b1  = (const float*)d_in[13];
    const float* w2  = (const float*)d_in[14];
    const float* b2  = (const float*)d_in[15];
    float* out = (float*)d_out;

    float *xz, *h1, *h2, *coef;
    u32 *f0, *f1, *f2, *fg0, *fg1, *fg2;
    cudaGetSymbolAddress((void**)&xz, g_xz);
    cudaGetSymbolAddress((void**)&h1, g_h1);
    cudaGetSymbolAddress((void**)&h2, g_h2);
    cudaGetSymbolAddress((void**)&coef, g_coef);
    cudaGetSymbolAddress((void**)&f0, g_f0);
    cudaGetSymbolAddress((void**)&f1, g_f1);
    cudaGetSymbolAddress((void**)&f2, g_f2);
    cudaGetSymbolAddress((void**)&fg0, g_fg0);
    cudaGetSymbolAddress((void**)&fg1, g_fg1);
    cudaGetSymbolAddress((void**)&fg2, g_fg2);

    const int SMG = 64 * 148 * 4 + 3 * 16384;            // 87040
    const int SM0 = 2048 + 64 * 84 * 4 + 3 * 8192;       // 48128
    const int SM1 = 2048 + 64 * 148 * 4 + 3 * 8192;      // 64512
    const int SM2 = 2048 + 64 * 148 * 4 + 3 * 4096;      // 52224
    cudaFuncSetAttribute(gating_kernel, cudaFuncAttributeMaxDynamicSharedMemorySize, SMG);
    cudaFuncSetAttribute(expert_kernel<DIN_, 5, 128, 1>, cudaFuncAttributeMaxDynamicSharedMemorySize, SM0);
    cudaFuncSetAttribute(expert_kernel<IN1_, 9, 128, 1>, cudaFuncAttributeMaxDynamicSharedMemorySize, SM1);
    cudaFuncSetAttribute(expert_kernel<IN1_, 9, 64,  0>, cudaFuncAttributeMaxDynamicSharedMemorySize, SM2);

    pack_kernel<<<592, 256>>>(x, z);
    wprep_kernel<<<296, 256>>>(w0, b0, w1, b1, w2, b2, gw0, gb0, gw1, gb1, gw2, gb2);

    gating_kernel<<<128, 256, SMG>>>(xz, fg0, fg1, fg2, gw3, gb3);

    expert_kernel<DIN_, 5, 128, 1><<<dim3(2, 128), 256, SM0>>>(xz, DIN_, f0, coef, h1, IN1_);
    expert_kernel<IN1_, 9, 128, 1><<<dim3(2, 128), 256, SM1>>>(h1, IN1_, f1, coef, h2, IN1_);
    expert_kernel<IN1_, 9, 64,  0><<<dim3(2, 128), 256, SM2>>>(h2, IN1_, f2, coef, out, NXT_);
}